// round 13
// baseline (speedup 1.0000x reference)
#include <cuda_runtime.h>
#include <cuda_bf16.h>
#include <math_constants.h>
#include <cstdint>

#define Bn  4
#define Sn  1024
#define Cn  2048
#define Hn  16
#define Dn  128
#define BSn (Bn*Sn)       // 4096
#define NQKV (3*Cn)       // 6144

// ---------------- scratch (device globals; no allocations allowed) ----------
// split-bf16 q/k/v in [bh][s][d]  (q pre-scaled by 1/sqrt(D))
__device__ __nv_bfloat16 g_qh[(size_t)Bn*Hn*Sn*Dn];
__device__ __nv_bfloat16 g_ql[(size_t)Bn*Hn*Sn*Dn];
__device__ __nv_bfloat16 g_kh[(size_t)Bn*Hn*Sn*Dn];
__device__ __nv_bfloat16 g_kl[(size_t)Bn*Hn*Sn*Dn];
__device__ __nv_bfloat16 g_vh[(size_t)Bn*Hn*Sn*Dn];
__device__ __nv_bfloat16 g_vl[(size_t)Bn*Hn*Sn*Dn];

// split-bf16 GEMM operands
__device__ __nv_bfloat16 g_xh[(size_t)BSn*Cn];
__device__ __nv_bfloat16 g_xl[(size_t)BSn*Cn];
__device__ __nv_bfloat16 g_oh[(size_t)BSn*Cn];     // attention out split
__device__ __nv_bfloat16 g_ol[(size_t)BSn*Cn];
__device__ __nv_bfloat16 g_wqkvT_h[(size_t)NQKV*Cn];   // [N,K]
__device__ __nv_bfloat16 g_wqkvT_l[(size_t)NQKV*Cn];
__device__ __nv_bfloat16 g_wprojT_h[(size_t)Cn*Cn];
__device__ __nv_bfloat16 g_wprojT_l[(size_t)Cn*Cn];

// =================== helpers ================================================
__device__ __forceinline__ uint32_t smem_to_u32(const void* p) {
    uint32_t a;
    asm("{ .reg .u64 t; cvta.to.shared.u64 t, %1; cvt.u32.u64 %0, t; }"
        : "=r"(a) : "l"(p));
    return a;
}
__device__ __forceinline__ void cp16(uint32_t dst, const void* src) {
    asm volatile("cp.async.cg.shared.global [%0], [%1], 16;" :: "r"(dst), "l"(src));
}
__device__ __forceinline__ void cp_commit() { asm volatile("cp.async.commit_group;"); }
__device__ __forceinline__ void cp_wait1()  { asm volatile("cp.async.wait_group 1;" ::: "memory"); }
__device__ __forceinline__ void cp_wait0()  { asm volatile("cp.async.wait_group 0;" ::: "memory"); }

__device__ __forceinline__ void ldm_x4(uint32_t* r, uint32_t addr) {
    asm volatile("ldmatrix.sync.aligned.m8n8.x4.shared.b16 {%0,%1,%2,%3}, [%4];"
        : "=r"(r[0]), "=r"(r[1]), "=r"(r[2]), "=r"(r[3]) : "r"(addr));
}
__device__ __forceinline__ void ldm_x4_t(uint32_t* r, uint32_t addr) {
    asm volatile("ldmatrix.sync.aligned.m8n8.x4.trans.shared.b16 {%0,%1,%2,%3}, [%4];"
        : "=r"(r[0]), "=r"(r[1]), "=r"(r[2]), "=r"(r[3]) : "r"(addr));
}
__device__ __forceinline__ void mma_bf16(float* d, const uint32_t* a, const uint32_t* b) {
    asm volatile(
        "mma.sync.aligned.m16n8k16.row.col.f32.bf16.bf16.f32 "
        "{%0,%1,%2,%3}, {%4,%5,%6,%7}, {%8,%9}, {%0,%1,%2,%3};"
        : "+f"(d[0]), "+f"(d[1]), "+f"(d[2]), "+f"(d[3])
        : "r"(a[0]), "r"(a[1]), "r"(a[2]), "r"(a[3]), "r"(b[0]), "r"(b[1]));
}
__device__ __forceinline__ uint32_t packh2(float e0, float e1) {
    __nv_bfloat162 t = __floats2bfloat162_rn(e0, e1);
    return *(uint32_t*)&t;
}
__device__ __forceinline__ void split2(float e0, float e1, uint32_t& hi, uint32_t& lo) {
    __nv_bfloat16 h0 = __float2bfloat16(e0), h1 = __float2bfloat16(e1);
    __nv_bfloat162 hp = __halves2bfloat162(h0, h1);
    hi = *(uint32_t*)&hp;
    lo = packh2(e0 - __bfloat162float(h0), e1 - __bfloat162float(h1));
}

// ---------------- shared GEMM mainloop (R10 ordering, x4 B loads) ------------
#define RS 40
#define STAGE_BYTES (4 * 128 * RS * 2)   // 40960 B

#define GEMM_FILL(stage, k0)                                                     \
    do {                                                                         \
        uint32_t sbf = sbase + (uint32_t)(stage) * STAGE_BYTES;                  \
        _Pragma("unroll")                                                        \
        for (int it = 0; it < 8; it++) {                                         \
            int idx = tid + it * 256;                                            \
            int arr = idx >> 9;                                                  \
            int rem = idx & 511;                                                 \
            int r = rem >> 2;                                                    \
            int ch = rem & 3;                                                    \
            uint32_t soff = (uint32_t)arr * (128 * RS * 2)                       \
                          + (uint32_t)r * (RS * 2) + (uint32_t)ch * 16;          \
            const __nv_bfloat16* src;                                            \
            if (arr == 0)      src = Ah + (size_t)(row0 + r) * K + (k0) + ch * 8;\
            else if (arr == 1) src = Al + (size_t)(row0 + r) * K + (k0) + ch * 8;\
            else if (arr == 2) src = Bh + (size_t)(col0 + r) * K + (k0) + ch * 8;\
            else               src = Bl + (size_t)(col0 + r) * K + (k0) + ch * 8;\
            cp16(sbf + soff, src);                                               \
        }                                                                        \
        cp_commit();                                                             \
    } while (0)

// fill(c+1) first, wait1, sync, ALL LDSM, sync, barrier-free MMA block.
// B fragments via ldm_x4: one x4 = both k-halves for a PAIR of nt tiles.
#define GEMM_MAINLOOP(NCexpr)                                                    \
    const int NC = (NCexpr);                                                     \
    GEMM_FILL(0, 0);                                                             \
    const int lm   = lane & 15;                                                  \
    const int lk8  = lane >> 4;                                                  \
    const int brw  = (lane & 7) + ((lane >> 4) << 3);   /* row-in-pair */        \
    const int bkh  = (lane >> 3) & 1;                   /* k half */             \
    for (int c = 0; c < NC; c++) {                                               \
        if (c + 1 < NC) GEMM_FILL((c + 1) & 1, (c + 1) << 5);                    \
        if (c + 1 < NC) cp_wait1(); else cp_wait0();                             \
        __syncthreads();                                                         \
        uint32_t sbf = sbase + (uint32_t)(c & 1) * STAGE_BYTES;                  \
        uint32_t sAh = sbf;                                                      \
        uint32_t sAl = sbf + 128 * RS * 2;                                       \
        uint32_t sBh = sbf + 2 * 128 * RS * 2;                                   \
        uint32_t sBl = sbf + 3 * 128 * RS * 2;                                   \
        uint32_t ah[2][4][4], al[2][4][4], bh4[2][2][4], bl4[2][2][4];           \
        _Pragma("unroll")                                                        \
        for (int ks = 0; ks < 2; ks++) {                                         \
            const int kc = ks * 16;                                              \
            _Pragma("unroll")                                                    \
            for (int mt = 0; mt < 4; mt++) {                                     \
                uint32_t roff = (uint32_t)(warp_m * 64 + mt * 16 + lm) * (RS * 2)\
                              + (uint32_t)(kc + lk8 * 8) * 2;                    \
                ldm_x4(ah[ks][mt], sAh + roff);                                  \
                ldm_x4(al[ks][mt], sAl + roff);                                  \
            }                                                                    \
            _Pragma("unroll")                                                    \
            for (int ntp = 0; ntp < 2; ntp++) {                                  \
                uint32_t roff = (uint32_t)(warp_n * 32 + ntp * 16 + brw) * (RS * 2)\
                              + (uint32_t)(kc + bkh * 8) * 2;                    \
                ldm_x4(bh4[ks][ntp], sBh + roff);                                \
                ldm_x4(bl4[ks][ntp], sBl + roff);                                \
            }                                                                    \
        }                                                                        \
        __syncthreads();                                                         \
        _Pragma("unroll")                                                        \
        for (int ks = 0; ks < 2; ks++)                                           \
            _Pragma("unroll")                                                    \
            for (int ntp = 0; ntp < 2; ntp++)                                    \
                _Pragma("unroll")                                                \
                for (int mt = 0; mt < 4; mt++) {                                 \
                    mma_bf16(acc[mt][2 * ntp],     ah[ks][mt], &bh4[ks][ntp][0]);\
                    mma_bf16(acc[mt][2 * ntp],     ah[ks][mt], &bl4[ks][ntp][0]);\
                    mma_bf16(acc[mt][2 * ntp],     al[ks][mt], &bh4[ks][ntp][0]);\
                    mma_bf16(acc[mt][2 * ntp + 1], ah[ks][mt], &bh4[ks][ntp][2]);\
                    mma_bf16(acc[mt][2 * ntp + 1], ah[ks][mt], &bl4[ks][ntp][2]);\
                    mma_bf16(acc[mt][2 * ntp + 1], al[ks][mt], &bh4[ks][ntp][2]);\
                }                                                                \
    }

// ---------------- plain GEMM (proj): fp32 out + bias -------------------------
__global__ __launch_bounds__(256, 2) void gemm_mma(
    const __nv_bfloat16* __restrict__ Ah, const __nv_bfloat16* __restrict__ Al,
    const __nv_bfloat16* __restrict__ Bh, const __nv_bfloat16* __restrict__ Bl,
    const float* __restrict__ bias, float* __restrict__ C,
    int M, int N, int K)
{
    extern __shared__ char dsm[];
    const uint32_t sbase = smem_to_u32(dsm);
    const int tid = threadIdx.x;
    const int wid = tid >> 5, lane = tid & 31;
    const int warp_m = wid >> 2;
    const int warp_n = wid & 3;
    const int row0 = blockIdx.y * 128;
    const int col0 = blockIdx.x * 128;

    float acc[4][4][4];
#pragma unroll
    for (int i = 0; i < 4; i++)
#pragma unroll
        for (int j = 0; j < 4; j++)
#pragma unroll
            for (int q = 0; q < 4; q++) acc[i][j][q] = 0.f;

    GEMM_MAINLOOP(K >> 5)

    const int qr = lane >> 2;
    const int qc = (lane & 3) * 2;
#pragma unroll
    for (int mt = 0; mt < 4; mt++) {
#pragma unroll
        for (int nt = 0; nt < 4; nt++) {
            int col = col0 + warp_n * 32 + nt * 8 + qc;
            float b0 = bias[col], b1 = bias[col + 1];
            int r0 = row0 + warp_m * 64 + mt * 16 + qr;
            float2 v0 = { acc[mt][nt][0] + b0, acc[mt][nt][1] + b1 };
            float2 v1 = { acc[mt][nt][2] + b0, acc[mt][nt][3] + b1 };
            *(float2*)&C[(size_t)r0 * N + col] = v0;
            *(float2*)&C[(size_t)(r0 + 8) * N + col] = v1;
        }
    }
}

// ---------------- fused QKV GEMM: + RMSNorm + RoPE + split bf16 --------------
// grid (48, 32): blockIdx.x = type*16 + head. Tile cols = one full head.
__global__ __launch_bounds__(256, 2) void gemm_qkv_fused(
    const __nv_bfloat16* __restrict__ Ah, const __nv_bfloat16* __restrict__ Al,
    const __nv_bfloat16* __restrict__ Bh, const __nv_bfloat16* __restrict__ Bl,
    const float* __restrict__ qw, const float* __restrict__ kw,
    const float* __restrict__ fcos, const float* __restrict__ fsin,
    int K)
{
    extern __shared__ char dsm[];
    const uint32_t sbase = smem_to_u32(dsm);
    const int tid = threadIdx.x;
    const int wid = tid >> 5, lane = tid & 31;
    const int warp_m = wid >> 2;
    const int warp_n = wid & 3;
    const int row0 = blockIdx.y * 128;
    const int col0 = blockIdx.x * 128;

    float acc[4][4][4];
#pragma unroll
    for (int i = 0; i < 4; i++)
#pragma unroll
        for (int j = 0; j < 4; j++)
#pragma unroll
            for (int q = 0; q < 4; q++) acc[i][j][q] = 0.f;

    GEMM_MAINLOOP(K >> 5)

    // ---- fused epilogue ----
    const int t  = blockIdx.x >> 4;     // 0=q, 1=k, 2=v
    const int hh = blockIdx.x & 15;
    const int qr = lane >> 2;
    const int qc = (lane & 3) * 2;

    __syncthreads();                    // MMA block done in all warps
    float* red = (float*)dsm;           // [128][4]

    float rstd[8];
#pragma unroll
    for (int j = 0; j < 8; j++) rstd[j] = 1.f;

    if (t < 2) {
#pragma unroll
        for (int mt = 0; mt < 4; mt++) {
#pragma unroll
            for (int half = 0; half < 2; half++) {
                float ss = 0.f;
#pragma unroll
                for (int nt = 0; nt < 4; nt++) {
                    float e = acc[mt][nt][half * 2], o_ = acc[mt][nt][half * 2 + 1];
                    ss += e * e + o_ * o_;
                }
                ss += __shfl_xor_sync(0xffffffffu, ss, 1);
                ss += __shfl_xor_sync(0xffffffffu, ss, 2);
                if ((lane & 3) == 0)
                    red[(warp_m * 64 + mt * 16 + half * 8 + qr) * 4 + warp_n] = ss;
            }
        }
        __syncthreads();
#pragma unroll
        for (int mt = 0; mt < 4; mt++)
#pragma unroll
            for (int half = 0; half < 2; half++) {
                int rl = warp_m * 64 + mt * 16 + half * 8 + qr;
                float tot = red[rl * 4] + red[rl * 4 + 1] + red[rl * 4 + 2] + red[rl * 4 + 3];
                rstd[mt * 2 + half] = rsqrtf(tot * (1.0f / Dn) + 1e-6f);
            }
    }

    const float* wnorm = (t == 0) ? qw : kw;
    const float tsc = (t == 0) ? 0.08838834764831845f : 1.0f;
    __nv_bfloat16* dh = (t == 0) ? g_qh : (t == 1 ? g_kh : g_vh);
    __nv_bfloat16* dl = (t == 0) ? g_ql : (t == 1 ? g_kl : g_vl);

#pragma unroll
    for (int mt = 0; mt < 4; mt++) {
#pragma unroll
        for (int half = 0; half < 2; half++) {
            int srow = row0 + warp_m * 64 + mt * 16 + half * 8 + qr;   // bs
            int b = srow >> 10, s = srow & 1023;
            size_t obase = ((size_t)(b * Hn + hh) * Sn + s) * Dn;
            float r = rstd[mt * 2 + half];
#pragma unroll
            for (int nt = 0; nt < 4; nt++) {
                int d0 = warp_n * 32 + nt * 8 + qc;
                float e  = acc[mt][nt][half * 2];
                float o_ = acc[mt][nt][half * 2 + 1];
                uint32_t hiw, low;
                if (t < 2) {
                    e  = e  * r * wnorm[d0];
                    o_ = o_ * r * wnorm[d0 + 1];
                    float cs = fcos[(size_t)srow * (Dn / 2) + (d0 >> 1)];
                    float sn = fsin[(size_t)srow * (Dn / 2) + (d0 >> 1)];
                    float re = (e * cs - o_ * sn) * tsc;
                    float im = (e * sn + o_ * cs) * tsc;
                    split2(re, im, hiw, low);
                } else {
                    split2(e, o_, hiw, low);
                }
                *(uint32_t*)&dh[obase + d0] = hiw;
                *(uint32_t*)&dl[obase + d0] = low;
            }
        }
    }
}

// ---------------- fp32 -> (hi, lo) bf16 split, elementwise -------------------
__global__ __launch_bounds__(256) void split_kernel(
    const float* __restrict__ in, __nv_bfloat16* __restrict__ hi,
    __nv_bfloat16* __restrict__ lo, int n)
{
    int i = blockIdx.x * blockDim.x + threadIdx.x;
    if (i < n) {
        float v = in[i];
        __nv_bfloat16 h = __float2bfloat16(v);
        float r = v - __bfloat162float(h);
        hi[i] = h;
        lo[i] = __float2bfloat16(r);
    }
}

// ---------------- transpose + split: W[K,N] -> T[N,K] hi/lo ------------------
__global__ __launch_bounds__(256) void transpose_split_kernel(
    const float* __restrict__ W, __nv_bfloat16* __restrict__ Th,
    __nv_bfloat16* __restrict__ Tl, int K, int N)
{
    __shared__ float t[32][33];
    int tx = threadIdx.x, ty = threadIdx.y;
    int n0 = blockIdx.x * 32, k0 = blockIdx.y * 32;
#pragma unroll
    for (int i = ty; i < 32; i += 8)
        t[i][tx] = W[(size_t)(k0 + i) * N + n0 + tx];
    __syncthreads();
#pragma unroll
    for (int i = ty; i < 32; i += 8) {
        float v = t[tx][i];
        __nv_bfloat16 h = __float2bfloat16(v);
        float r = v - __bfloat162float(h);
        size_t o = (size_t)(n0 + i) * K + k0 + tx;
        Th[o] = h;
        Tl[o] = __float2bfloat16(r);
    }
}

// ---------------- flash attention via mma.sync split-bf16 (R8 loop) ----------
#define ARS   136                    // smem row stride (bf16 elems) = 272 B
#define ATILE (64 * ARS * 2)         // 17408
#define AQT   (128 * ARS * 2)        // 34816

__global__ __launch_bounds__(256) void attn_mma()
{
    extern __shared__ char asmem[];
    const uint32_t sb = smem_to_u32(asmem);
    const uint32_t sQh = sb;
    const uint32_t sQl = sb + AQT;
    const uint32_t sStage = sb + 2 * AQT;

    const int tid = threadIdx.x;
    const int wid = tid >> 5, lane = tid & 31;
    const int bh = blockIdx.y;
    const int q0 = blockIdx.x * 128;
    const int b = bh / Hn, h = bh % Hn;

    const __nv_bfloat16* qh = g_qh + (size_t)bh * Sn * Dn;
    const __nv_bfloat16* ql = g_ql + (size_t)bh * Sn * Dn;
    const __nv_bfloat16* kh = g_kh + (size_t)bh * Sn * Dn;
    const __nv_bfloat16* kl = g_kl + (size_t)bh * Sn * Dn;
    const __nv_bfloat16* vh = g_vh + (size_t)bh * Sn * Dn;
    const __nv_bfloat16* vl = g_vl + (size_t)bh * Sn * Dn;

#pragma unroll
    for (int it = 0; it < 16; it++) {
        int idx = tid + it * 256;
        int arr = idx >> 11;
        int rem = idx & 2047;
        int r = rem >> 4, ch = rem & 15;
        const __nv_bfloat16* src = (arr ? ql : qh) + (size_t)(q0 + r) * Dn + ch * 8;
        cp16((arr ? sQl : sQh) + (uint32_t)r * (ARS * 2) + (uint32_t)ch * 16, src);
    }

    auto fill = [&](int stage, int c) {
        uint32_t base = sStage + (uint32_t)stage * 4 * ATILE;
        int k0 = c * 64;
#pragma unroll
        for (int it = 0; it < 16; it++) {
            int idx = tid + it * 256;
            int arr = idx >> 10;
            int rem = idx & 1023;
            int r = rem >> 4, ch = rem & 15;
            const __nv_bfloat16* s =
                (arr == 0 ? kh : arr == 1 ? kl : arr == 2 ? vh : vl)
                + (size_t)(k0 + r) * Dn + ch * 8;
            cp16(base + (uint32_t)arr * ATILE + (uint32_t)r * (ARS * 2) + (uint32_t)ch * 16, s);
        }
        cp_commit();
    };

    fill(0, 0);   // group also contains q loads

    float o[16][4];
#pragma unroll
    for (int i = 0; i < 16; i++)
#pragma unroll
        for (int j = 0; j < 4; j++) o[i][j] = 0.f;
    float m0 = -CUDART_INF_F, m1 = -CUDART_INF_F, l0 = 0.f, l1 = 0.f;

    const int arow = wid * 16 + (lane & 15);
    const uint32_t aoff_base = (uint32_t)arow * (ARS * 2) + (uint32_t)((lane >> 4) * 8) * 2;
    const int brow = (lane & 7) + ((lane >> 4) << 3);
    const int vkey = (lane & 7) + (((lane >> 3) & 1) << 3);
    const uint32_t vcolb = (uint32_t)((lane >> 4) << 3) * 2;

    for (int c = 0; c < 16; c++) {
        if (c + 1 < 16) fill((c + 1) & 1, c + 1);
        if (c + 1 < 16) cp_wait1(); else cp_wait0();
        __syncthreads();

        uint32_t st = sStage + (uint32_t)(c & 1) * 4 * ATILE;
        uint32_t sKh = st, sKl = st + ATILE, sVh = st + 2 * ATILE, sVl = st + 3 * ATILE;

        float s[8][4];
#pragma unroll
        for (int i = 0; i < 8; i++)
#pragma unroll
            for (int j = 0; j < 4; j++) s[i][j] = 0.f;

#pragma unroll
        for (int ks = 0; ks < 8; ks++) {
            const int kc = ks * 16;
            uint32_t ah[4], al[4];
            uint32_t aoff = aoff_base + (uint32_t)kc * 2;
            ldm_x4(ah, sQh + aoff);
            ldm_x4(al, sQl + aoff);
            const uint32_t bcol = (uint32_t)(kc + ((lane >> 3) & 1) * 8) * 2;
#pragma unroll
            for (int np = 0; np < 4; np++) {
                uint32_t bh4[4], bl4[4];
                uint32_t boff = (uint32_t)(np * 16 + brow) * (ARS * 2) + bcol;
                ldm_x4(bh4, sKh + boff);
                ldm_x4(bl4, sKl + boff);
                mma_bf16(s[2 * np],     ah, &bh4[0]);
                mma_bf16(s[2 * np],     ah, &bl4[0]);
                mma_bf16(s[2 * np],     al, &bh4[0]);
                mma_bf16(s[2 * np + 1], ah, &bh4[2]);
                mma_bf16(s[2 * np + 1], ah, &bl4[2]);
                mma_bf16(s[2 * np + 1], al, &bh4[2]);
            }
        }

        float tmax0 = -CUDART_INF_F, tmax1 = -CUDART_INF_F;
#pragma unroll
        for (int nt = 0; nt < 8; nt++) {
            tmax0 = fmaxf(tmax0, fmaxf(s[nt][0], s[nt][1]));
            tmax1 = fmaxf(tmax1, fmaxf(s[nt][2], s[nt][3]));
        }
        tmax0 = fmaxf(tmax0, __shfl_xor_sync(0xffffffffu, tmax0, 1));
        tmax0 = fmaxf(tmax0, __shfl_xor_sync(0xffffffffu, tmax0, 2));
        tmax1 = fmaxf(tmax1, __shfl_xor_sync(0xffffffffu, tmax1, 1));
        tmax1 = fmaxf(tmax1, __shfl_xor_sync(0xffffffffu, tmax1, 2));
        float mn0 = fmaxf(m0, tmax0), mn1 = fmaxf(m1, tmax1);
        float al0 = __expf(m0 - mn0), al1 = __expf(m1 - mn1);
        m0 = mn0; m1 = mn1;
        float ps0 = 0.f, ps1 = 0.f;
#pragma unroll
        for (int nt = 0; nt < 8; nt++) {
            s[nt][0] = __expf(s[nt][0] - mn0);
            s[nt][1] = __expf(s[nt][1] - mn0);
            s[nt][2] = __expf(s[nt][2] - mn1);
            s[nt][3] = __expf(s[nt][3] - mn1);
            ps0 += s[nt][0] + s[nt][1];
            ps1 += s[nt][2] + s[nt][3];
        }
        l0 = l0 * al0 + ps0;
        l1 = l1 * al1 + ps1;
#pragma unroll
        for (int i = 0; i < 16; i++) {
            o[i][0] *= al0; o[i][1] *= al0;
            o[i][2] *= al1; o[i][3] *= al1;
        }

#pragma unroll
        for (int k2 = 0; k2 < 4; k2++) {
            uint32_t aPh[4], aPl[4];
            split2(s[2 * k2][0],     s[2 * k2][1],     aPh[0], aPl[0]);
            split2(s[2 * k2][2],     s[2 * k2][3],     aPh[1], aPl[1]);
            split2(s[2 * k2 + 1][0], s[2 * k2 + 1][1], aPh[2], aPl[2]);
            split2(s[2 * k2 + 1][2], s[2 * k2 + 1][3], aPh[3], aPl[3]);
            const uint32_t vrow = (uint32_t)(k2 * 16 + vkey) * (ARS * 2);
#pragma unroll
            for (int np = 0; np < 8; np++) {
                uint32_t bvh[4], bvl[4];
                uint32_t voff = vrow + (uint32_t)(np * 16) * 2 + vcolb;
                ldm_x4_t(bvh, sVh + voff);
                ldm_x4_t(bvl, sVl + voff);
                mma_bf16(o[2 * np],     aPh, &bvh[0]);
                mma_bf16(o[2 * np],     aPh, &bvl[0]);
                mma_bf16(o[2 * np],     aPl, &bvh[0]);
                mma_bf16(o[2 * np + 1], aPh, &bvh[2]);
                mma_bf16(o[2 * np + 1], aPh, &bvl[2]);
                mma_bf16(o[2 * np + 1], aPl, &bvh[2]);
            }
        }
        __syncthreads();
    }

    l0 += __shfl_xor_sync(0xffffffffu, l0, 1);
    l0 += __shfl_xor_sync(0xffffffffu, l0, 2);
    l1 += __shfl_xor_sync(0xffffffffu, l1, 1);
    l1 += __shfl_xor_sync(0xffffffffu, l1, 2);
    float inv0 = 1.f / l0, inv1 = 1.f / l1;

    const int row0 = q0 + wid * 16 + (lane >> 2);
    const int colb = (lane & 3) * 2;
#pragma unroll
    for (int nt = 0; nt < 16; nt++) {
        int col = nt * 8 + colb;
        size_t i0 = (size_t)(b * Sn + row0) * Cn + h * Dn + col;
        size_t i1 = (size_t)(b * Sn + row0 + 8) * Cn + h * Dn + col;
        uint32_t h0, lo0, h1, lo1;
        split2(o[nt][0] * inv0, o[nt][1] * inv0, h0, lo0);
        split2(o[nt][2] * inv1, o[nt][3] * inv1, h1, lo1);
        *(uint32_t*)&g_oh[i0] = h0;
        *(uint32_t*)&g_ol[i0] = lo0;
        *(uint32_t*)&g_oh[i1] = h1;
        *(uint32_t*)&g_ol[i1] = lo1;
    }
}

// ---------------- launch ----------------------------------------------------
extern "C" void kernel_launch(void* const* d_in, const int* in_sizes, int n_in,
                              void* d_out, int out_size)
{
    const float* x      = (const float*)d_in[0];
    const float* W_qkv  = (const float*)d_in[1];
    const float* q_w    = (const float*)d_in[2];
    const float* k_w    = (const float*)d_in[3];
    const float* W_proj = (const float*)d_in[4];
    const float* b_proj = (const float*)d_in[5];
    const float* fcos   = (const float*)d_in[6];
    const float* fsin   = (const float*)d_in[7];
    float* out = (float*)d_out;

    __nv_bfloat16 *p_xh, *p_xl, *p_oh, *p_ol;
    __nv_bfloat16 *p_wqh, *p_wql, *p_wph, *p_wpl;
    cudaGetSymbolAddress((void**)&p_xh,  g_xh);
    cudaGetSymbolAddress((void**)&p_xl,  g_xl);
    cudaGetSymbolAddress((void**)&p_oh,  g_oh);
    cudaGetSymbolAddress((void**)&p_ol,  g_ol);
    cudaGetSymbolAddress((void**)&p_wqh, g_wqkvT_h);
    cudaGetSymbolAddress((void**)&p_wql, g_wqkvT_l);
    cudaGetSymbolAddress((void**)&p_wph, g_wprojT_h);
    cudaGetSymbolAddress((void**)&p_wpl, g_wprojT_l);

    constexpr int GEMM_SMEM = 2 * STAGE_BYTES;            // 81920 B
    constexpr int ATTN_SMEM = 2 * AQT + 2 * 4 * ATILE;    // 208896 B
    static bool attr_set = false;
    if (!attr_set) {
        cudaFuncSetAttribute(gemm_mma, cudaFuncAttributeMaxDynamicSharedMemorySize, GEMM_SMEM);
        cudaFuncSetAttribute(gemm_qkv_fused, cudaFuncAttributeMaxDynamicSharedMemorySize, GEMM_SMEM);
        cudaFuncSetAttribute(attn_mma, cudaFuncAttributeMaxDynamicSharedMemorySize, ATTN_SMEM);
        attr_set = true;
    }

    // 0) operand conversions
    {
        int n = BSn * Cn;
        split_kernel<<<(n + 255) / 256, 256>>>(x, p_xh, p_xl, n);
        dim3 blk(32, 8);
        transpose_split_kernel<<<dim3(NQKV / 32, Cn / 32), blk>>>(W_qkv, p_wqh, p_wql, Cn, NQKV);
        transpose_split_kernel<<<dim3(Cn / 32, Cn / 32), blk>>>(W_proj, p_wph, p_wpl, Cn, Cn);
    }
    // 1) qkv = x @ W_qkv, fused with rmsnorm + rope + split
    {
        dim3 grid(NQKV / 128, BSn / 128);
        gemm_qkv_fused<<<grid, 256, GEMM_SMEM>>>(p_xh, p_xl, p_wqh, p_wql,
                                                 q_w, k_w, fcos, fsin, Cn);
    }
    // 2) attention (mma.sync)
    {
        dim3 grid(Sn / 128, Bn * Hn);
        attn_mma<<<grid, 256, ATTN_SMEM>>>();
    }
    // 3) out = o @ W_proj + b_proj
    {
        dim3 grid(Cn / 128, BSn / 128);
        gemm_mma<<<grid, 256, GEMM_SMEM>>>(p_oh, p_ol, p_wph, p_wpl, b_proj, out,
                                           BSn, Cn, Cn);
    }
}

// round 14
// speedup vs baseline: 1.0038x; 1.0038x over previous
#include <cuda_runtime.h>
#include <cuda_bf16.h>
#include <math_constants.h>
#include <cstdint>

#define Bn  4
#define Sn  1024
#define Cn  2048
#define Hn  16
#define Dn  128
#define BSn (Bn*Sn)       // 4096
#define NQKV (3*Cn)       // 6144

// ---------------- scratch (device globals; no allocations allowed) ----------
// split-bf16 q/k/v in [bh][s][d]  (q pre-scaled by 1/sqrt(D))
__device__ __nv_bfloat16 g_qh[(size_t)Bn*Hn*Sn*Dn];
__device__ __nv_bfloat16 g_ql[(size_t)Bn*Hn*Sn*Dn];
__device__ __nv_bfloat16 g_kh[(size_t)Bn*Hn*Sn*Dn];
__device__ __nv_bfloat16 g_kl[(size_t)Bn*Hn*Sn*Dn];
__device__ __nv_bfloat16 g_vh[(size_t)Bn*Hn*Sn*Dn];
__device__ __nv_bfloat16 g_vl[(size_t)Bn*Hn*Sn*Dn];

// split-bf16 GEMM operands
__device__ __nv_bfloat16 g_xh[(size_t)BSn*Cn];
__device__ __nv_bfloat16 g_xl[(size_t)BSn*Cn];
__device__ __nv_bfloat16 g_oh[(size_t)BSn*Cn];     // attention out split
__device__ __nv_bfloat16 g_ol[(size_t)BSn*Cn];
__device__ __nv_bfloat16 g_wqkvT_h[(size_t)NQKV*Cn];   // [N,K]
__device__ __nv_bfloat16 g_wqkvT_l[(size_t)NQKV*Cn];
__device__ __nv_bfloat16 g_wprojT_h[(size_t)Cn*Cn];
__device__ __nv_bfloat16 g_wprojT_l[(size_t)Cn*Cn];

// =================== helpers ================================================
__device__ __forceinline__ uint32_t smem_to_u32(const void* p) {
    uint32_t a;
    asm("{ .reg .u64 t; cvta.to.shared.u64 t, %1; cvt.u32.u64 %0, t; }"
        : "=r"(a) : "l"(p));
    return a;
}
__device__ __forceinline__ void cp16(uint32_t dst, const void* src) {
    asm volatile("cp.async.cg.shared.global [%0], [%1], 16;" :: "r"(dst), "l"(src));
}
__device__ __forceinline__ void cp_commit() { asm volatile("cp.async.commit_group;"); }
__device__ __forceinline__ void cp_wait1()  { asm volatile("cp.async.wait_group 1;" ::: "memory"); }
__device__ __forceinline__ void cp_wait0()  { asm volatile("cp.async.wait_group 0;" ::: "memory"); }

__device__ __forceinline__ void ldm_x4(uint32_t* r, uint32_t addr) {
    asm volatile("ldmatrix.sync.aligned.m8n8.x4.shared.b16 {%0,%1,%2,%3}, [%4];"
        : "=r"(r[0]), "=r"(r[1]), "=r"(r[2]), "=r"(r[3]) : "r"(addr));
}
__device__ __forceinline__ void ldm_x4_t(uint32_t* r, uint32_t addr) {
    asm volatile("ldmatrix.sync.aligned.m8n8.x4.trans.shared.b16 {%0,%1,%2,%3}, [%4];"
        : "=r"(r[0]), "=r"(r[1]), "=r"(r[2]), "=r"(r[3]) : "r"(addr));
}
__device__ __forceinline__ void mma_bf16(float* d, const uint32_t* a, const uint32_t* b) {
    asm volatile(
        "mma.sync.aligned.m16n8k16.row.col.f32.bf16.bf16.f32 "
        "{%0,%1,%2,%3}, {%4,%5,%6,%7}, {%8,%9}, {%0,%1,%2,%3};"
        : "+f"(d[0]), "+f"(d[1]), "+f"(d[2]), "+f"(d[3])
        : "r"(a[0]), "r"(a[1]), "r"(a[2]), "r"(a[3]), "r"(b[0]), "r"(b[1]));
}
__device__ __forceinline__ uint32_t packh2(float e0, float e1) {
    __nv_bfloat162 t = __floats2bfloat162_rn(e0, e1);
    return *(uint32_t*)&t;
}
__device__ __forceinline__ void split2(float e0, float e1, uint32_t& hi, uint32_t& lo) {
    __nv_bfloat16 h0 = __float2bfloat16(e0), h1 = __float2bfloat16(e1);
    __nv_bfloat162 hp = __halves2bfloat162(h0, h1);
    hi = *(uint32_t*)&hp;
    lo = packh2(e0 - __bfloat162float(h0), e1 - __bfloat162float(h1));
}

// ---------------- shared GEMM mainloop -------------------------------------
#define RS 40
#define ARRB (128 * RS * 2)              // one array block: 10240 B
#define STAGE_BYTES (4 * ARRB)           // 40960 B

// Per-thread loop-invariant fill addressing:
//   it 0..7 -> arr = it/2, row = (it&1)? fr+64 : fr, fixed ch.
#define GEMM_FILL(stage, k0)                                                     \
    do {                                                                         \
        uint32_t sbf = sbase + (uint32_t)(stage) * STAGE_BYTES;                  \
        cp16(sbf + fso,             Ah + offA + (k0));                           \
        cp16(sbf + fso2,            Ah + offA + (size_t)64 * K + (k0));          \
        cp16(sbf + ARRB + fso,      Al + offA + (k0));                           \
        cp16(sbf + ARRB + fso2,     Al + offA + (size_t)64 * K + (k0));          \
        cp16(sbf + 2 * ARRB + fso,  Bh + offB + (k0));                           \
        cp16(sbf + 2 * ARRB + fso2, Bh + offB + (size_t)64 * K + (k0));          \
        cp16(sbf + 3 * ARRB + fso,  Bl + offB + (k0));                           \
        cp16(sbf + 3 * ARRB + fso2, Bl + offB + (size_t)64 * K + (k0));          \
        cp_commit();                                                             \
    } while (0)

// Body: LDSM(ks0) -> MMA(ks0) -> LDSM(ks1) -> sync (WAR guard) -> MMA(ks1).
// MMA(ks0) overlaps the LDSM(ks1) burst and absorbs the barrier wait.
#define GEMM_LDSM(ks, AH, AL, BH, BL)                                            \
    do {                                                                         \
        const int kc = (ks) * 16;                                                \
        _Pragma("unroll")                                                        \
        for (int mt = 0; mt < 4; mt++) {                                         \
            uint32_t roff = (uint32_t)(warp_m * 64 + mt * 16 + lm) * (RS * 2)    \
                          + (uint32_t)(kc + lk8 * 8) * 2;                        \
            ldm_x4(AH[mt], sAh + roff);                                          \
            ldm_x4(AL[mt], sAl + roff);                                          \
        }                                                                        \
        _Pragma("unroll")                                                        \
        for (int ntp = 0; ntp < 2; ntp++) {                                      \
            uint32_t roff = (uint32_t)(warp_n * 32 + ntp * 16 + brw) * (RS * 2)  \
                          + (uint32_t)(kc + bkh * 8) * 2;                        \
            ldm_x4(BH[ntp], sBh + roff);                                         \
            ldm_x4(BL[ntp], sBl + roff);                                         \
        }                                                                        \
    } while (0)

#define GEMM_MMAS(AH, AL, BH, BL)                                                \
    do {                                                                         \
        _Pragma("unroll")                                                        \
        for (int ntp = 0; ntp < 2; ntp++)                                        \
            _Pragma("unroll")                                                    \
            for (int mt = 0; mt < 4; mt++) {                                     \
                mma_bf16(acc[mt][2 * ntp],     AH[mt], &BH[ntp][0]);             \
                mma_bf16(acc[mt][2 * ntp],     AH[mt], &BL[ntp][0]);             \
                mma_bf16(acc[mt][2 * ntp],     AL[mt], &BH[ntp][0]);             \
                mma_bf16(acc[mt][2 * ntp + 1], AH[mt], &BH[ntp][2]);             \
                mma_bf16(acc[mt][2 * ntp + 1], AH[mt], &BL[ntp][2]);             \
                mma_bf16(acc[mt][2 * ntp + 1], AL[mt], &BH[ntp][2]);             \
            }                                                                    \
    } while (0)

#define GEMM_MAINLOOP(NCexpr)                                                    \
    const int NC = (NCexpr);                                                     \
    const int lm   = lane & 15;                                                  \
    const int lk8  = lane >> 4;                                                  \
    const int brw  = (lane & 7) + ((lane >> 4) << 3);                            \
    const int bkh  = (lane >> 3) & 1;                                            \
    const int fr   = tid >> 2;                                                   \
    const int fch  = tid & 3;                                                    \
    const size_t offA = (size_t)(row0 + fr) * K + fch * 8;                       \
    const size_t offB = (size_t)(col0 + fr) * K + fch * 8;                       \
    const uint32_t fso  = (uint32_t)fr * (RS * 2) + (uint32_t)fch * 16;          \
    const uint32_t fso2 = fso + 64u * (RS * 2);                                  \
    GEMM_FILL(0, 0);                                                             \
    for (int c = 0; c < NC; c++) {                                               \
        if (c + 1 < NC) GEMM_FILL((c + 1) & 1, (c + 1) << 5);                    \
        if (c + 1 < NC) cp_wait1(); else cp_wait0();                             \
        __syncthreads();                                                         \
        uint32_t sbf = sbase + (uint32_t)(c & 1) * STAGE_BYTES;                  \
        uint32_t sAh = sbf;                                                      \
        uint32_t sAl = sbf + ARRB;                                               \
        uint32_t sBh = sbf + 2 * ARRB;                                           \
        uint32_t sBl = sbf + 3 * ARRB;                                           \
        {                                                                        \
            uint32_t ah0[4][4], al0[4][4], bh0[2][4], bl0[2][4];                 \
            GEMM_LDSM(0, ah0, al0, bh0, bl0);                                    \
            GEMM_MMAS(ah0, al0, bh0, bl0);                                       \
        }                                                                        \
        {                                                                        \
            uint32_t ah1[4][4], al1[4][4], bh1[2][4], bl1[2][4];                 \
            GEMM_LDSM(1, ah1, al1, bh1, bl1);                                    \
            __syncthreads();                                                     \
            GEMM_MMAS(ah1, al1, bh1, bl1);                                       \
        }                                                                        \
    }

// ---------------- plain GEMM (proj): fp32 out + bias -------------------------
__global__ __launch_bounds__(256, 2) void gemm_mma(
    const __nv_bfloat16* __restrict__ Ah, const __nv_bfloat16* __restrict__ Al,
    const __nv_bfloat16* __restrict__ Bh, const __nv_bfloat16* __restrict__ Bl,
    const float* __restrict__ bias, float* __restrict__ C,
    int M, int N, int K)
{
    extern __shared__ char dsm[];
    const uint32_t sbase = smem_to_u32(dsm);
    const int tid = threadIdx.x;
    const int wid = tid >> 5, lane = tid & 31;
    const int warp_m = wid >> 2;
    const int warp_n = wid & 3;
    const int row0 = blockIdx.y * 128;
    const int col0 = blockIdx.x * 128;

    float acc[4][4][4];
#pragma unroll
    for (int i = 0; i < 4; i++)
#pragma unroll
        for (int j = 0; j < 4; j++)
#pragma unroll
            for (int q = 0; q < 4; q++) acc[i][j][q] = 0.f;

    GEMM_MAINLOOP(K >> 5)

    const int qr = lane >> 2;
    const int qc = (lane & 3) * 2;
#pragma unroll
    for (int mt = 0; mt < 4; mt++) {
#pragma unroll
        for (int nt = 0; nt < 4; nt++) {
            int col = col0 + warp_n * 32 + nt * 8 + qc;
            float b0 = bias[col], b1 = bias[col + 1];
            int r0 = row0 + warp_m * 64 + mt * 16 + qr;
            float2 v0 = { acc[mt][nt][0] + b0, acc[mt][nt][1] + b1 };
            float2 v1 = { acc[mt][nt][2] + b0, acc[mt][nt][3] + b1 };
            *(float2*)&C[(size_t)r0 * N + col] = v0;
            *(float2*)&C[(size_t)(r0 + 8) * N + col] = v1;
        }
    }
}

// ---------------- fused QKV GEMM: + RMSNorm + RoPE + split bf16 --------------
// grid (48, 32): blockIdx.x = type*16 + head. Tile cols = one full head.
__global__ __launch_bounds__(256, 2) void gemm_qkv_fused(
    const __nv_bfloat16* __restrict__ Ah, const __nv_bfloat16* __restrict__ Al,
    const __nv_bfloat16* __restrict__ Bh, const __nv_bfloat16* __restrict__ Bl,
    const float* __restrict__ qw, const float* __restrict__ kw,
    const float* __restrict__ fcos, const float* __restrict__ fsin,
    int K)
{
    extern __shared__ char dsm[];
    const uint32_t sbase = smem_to_u32(dsm);
    const int tid = threadIdx.x;
    const int wid = tid >> 5, lane = tid & 31;
    const int warp_m = wid >> 2;
    const int warp_n = wid & 3;
    const int row0 = blockIdx.y * 128;
    const int col0 = blockIdx.x * 128;

    float acc[4][4][4];
#pragma unroll
    for (int i = 0; i < 4; i++)
#pragma unroll
        for (int j = 0; j < 4; j++)
#pragma unroll
            for (int q = 0; q < 4; q++) acc[i][j][q] = 0.f;

    GEMM_MAINLOOP(K >> 5)

    // ---- fused epilogue ----
    const int t  = blockIdx.x >> 4;     // 0=q, 1=k, 2=v
    const int hh = blockIdx.x & 15;
    const int qr = lane >> 2;
    const int qc = (lane & 3) * 2;

    __syncthreads();                    // MMA block done in all warps
    float* red = (float*)dsm;           // [128][4]

    float rstd[8];
#pragma unroll
    for (int j = 0; j < 8; j++) rstd[j] = 1.f;

    if (t < 2) {
#pragma unroll
        for (int mt = 0; mt < 4; mt++) {
#pragma unroll
            for (int half = 0; half < 2; half++) {
                float ss = 0.f;
#pragma unroll
                for (int nt = 0; nt < 4; nt++) {
                    float e = acc[mt][nt][half * 2], o_ = acc[mt][nt][half * 2 + 1];
                    ss += e * e + o_ * o_;
                }
                ss += __shfl_xor_sync(0xffffffffu, ss, 1);
                ss += __shfl_xor_sync(0xffffffffu, ss, 2);
                if ((lane & 3) == 0)
                    red[(warp_m * 64 + mt * 16 + half * 8 + qr) * 4 + warp_n] = ss;
            }
        }
        __syncthreads();
#pragma unroll
        for (int mt = 0; mt < 4; mt++)
#pragma unroll
            for (int half = 0; half < 2; half++) {
                int rl = warp_m * 64 + mt * 16 + half * 8 + qr;
                float tot = red[rl * 4] + red[rl * 4 + 1] + red[rl * 4 + 2] + red[rl * 4 + 3];
                rstd[mt * 2 + half] = rsqrtf(tot * (1.0f / Dn) + 1e-6f);
            }
    }

    const float* wnorm = (t == 0) ? qw : kw;
    const float tsc = (t == 0) ? 0.08838834764831845f : 1.0f;
    __nv_bfloat16* dh = (t == 0) ? g_qh : (t == 1 ? g_kh : g_vh);
    __nv_bfloat16* dl = (t == 0) ? g_ql : (t == 1 ? g_kl : g_vl);

#pragma unroll
    for (int mt = 0; mt < 4; mt++) {
#pragma unroll
        for (int half = 0; half < 2; half++) {
            int srow = row0 + warp_m * 64 + mt * 16 + half * 8 + qr;   // bs
            int b = srow >> 10, s = srow & 1023;
            size_t obase = ((size_t)(b * Hn + hh) * Sn + s) * Dn;
            float r = rstd[mt * 2 + half];
#pragma unroll
            for (int nt = 0; nt < 4; nt++) {
                int d0 = warp_n * 32 + nt * 8 + qc;
                float e  = acc[mt][nt][half * 2];
                float o_ = acc[mt][nt][half * 2 + 1];
                uint32_t hiw, low;
                if (t < 2) {
                    e  = e  * r * wnorm[d0];
                    o_ = o_ * r * wnorm[d0 + 1];
                    float cs = fcos[(size_t)srow * (Dn / 2) + (d0 >> 1)];
                    float sn = fsin[(size_t)srow * (Dn / 2) + (d0 >> 1)];
                    float re = (e * cs - o_ * sn) * tsc;
                    float im = (e * sn + o_ * cs) * tsc;
                    split2(re, im, hiw, low);
                } else {
                    split2(e, o_, hiw, low);
                }
                *(uint32_t*)&dh[obase + d0] = hiw;
                *(uint32_t*)&dl[obase + d0] = low;
            }
        }
    }
}

// ---------------- fp32 -> (hi, lo) bf16 split, elementwise -------------------
__global__ __launch_bounds__(256) void split_kernel(
    const float* __restrict__ in, __nv_bfloat16* __restrict__ hi,
    __nv_bfloat16* __restrict__ lo, int n)
{
    int i = blockIdx.x * blockDim.x + threadIdx.x;
    if (i < n) {
        float v = in[i];
        __nv_bfloat16 h = __float2bfloat16(v);
        float r = v - __bfloat162float(h);
        hi[i] = h;
        lo[i] = __float2bfloat16(r);
    }
}

// ---------------- transpose + split: W[K,N] -> T[N,K] hi/lo ------------------
__global__ __launch_bounds__(256) void transpose_split_kernel(
    const float* __restrict__ W, __nv_bfloat16* __restrict__ Th,
    __nv_bfloat16* __restrict__ Tl, int K, int N)
{
    __shared__ float t[32][33];
    int tx = threadIdx.x, ty = threadIdx.y;
    int n0 = blockIdx.x * 32, k0 = blockIdx.y * 32;
#pragma unroll
    for (int i = ty; i < 32; i += 8)
        t[i][tx] = W[(size_t)(k0 + i) * N + n0 + tx];
    __syncthreads();
#pragma unroll
    for (int i = ty; i < 32; i += 8) {
        float v = t[tx][i];
        __nv_bfloat16 h = __float2bfloat16(v);
        float r = v - __bfloat162float(h);
        size_t o = (size_t)(n0 + i) * K + k0 + tx;
        Th[o] = h;
        Tl[o] = __float2bfloat16(r);
    }
}

// ---------------- flash attention via mma.sync split-bf16 (R8 loop) ----------
#define ARS   136                    // smem row stride (bf16 elems) = 272 B
#define ATILE (64 * ARS * 2)         // 17408
#define AQT   (128 * ARS * 2)        // 34816

__global__ __launch_bounds__(256) void attn_mma()
{
    extern __shared__ char asmem[];
    const uint32_t sb = smem_to_u32(asmem);
    const uint32_t sQh = sb;
    const uint32_t sQl = sb + AQT;
    const uint32_t sStage = sb + 2 * AQT;

    const int tid = threadIdx.x;
    const int wid = tid >> 5, lane = tid & 31;
    const int bh = blockIdx.y;
    const int q0 = blockIdx.x * 128;
    const int b = bh / Hn, h = bh % Hn;

    const __nv_bfloat16* qh = g_qh + (size_t)bh * Sn * Dn;
    const __nv_bfloat16* ql = g_ql + (size_t)bh * Sn * Dn;
    const __nv_bfloat16* kh = g_kh + (size_t)bh * Sn * Dn;
    const __nv_bfloat16* kl = g_kl + (size_t)bh * Sn * Dn;
    const __nv_bfloat16* vh = g_vh + (size_t)bh * Sn * Dn;
    const __nv_bfloat16* vl = g_vl + (size_t)bh * Sn * Dn;

#pragma unroll
    for (int it = 0; it < 16; it++) {
        int idx = tid + it * 256;
        int arr = idx >> 11;
        int rem = idx & 2047;
        int r = rem >> 4, ch = rem & 15;
        const __nv_bfloat16* src = (arr ? ql : qh) + (size_t)(q0 + r) * Dn + ch * 8;
        cp16((arr ? sQl : sQh) + (uint32_t)r * (ARS * 2) + (uint32_t)ch * 16, src);
    }

    auto fill = [&](int stage, int c) {
        uint32_t base = sStage + (uint32_t)stage * 4 * ATILE;
        int k0 = c * 64;
#pragma unroll
        for (int it = 0; it < 16; it++) {
            int idx = tid + it * 256;
            int arr = idx >> 10;
            int rem = idx & 1023;
            int r = rem >> 4, ch = rem & 15;
            const __nv_bfloat16* s =
                (arr == 0 ? kh : arr == 1 ? kl : arr == 2 ? vh : vl)
                + (size_t)(k0 + r) * Dn + ch * 8;
            cp16(base + (uint32_t)arr * ATILE + (uint32_t)r * (ARS * 2) + (uint32_t)ch * 16, s);
        }
        cp_commit();
    };

    fill(0, 0);   // group also contains q loads

    float o[16][4];
#pragma unroll
    for (int i = 0; i < 16; i++)
#pragma unroll
        for (int j = 0; j < 4; j++) o[i][j] = 0.f;
    float m0 = -CUDART_INF_F, m1 = -CUDART_INF_F, l0 = 0.f, l1 = 0.f;

    const int arow = wid * 16 + (lane & 15);
    const uint32_t aoff_base = (uint32_t)arow * (ARS * 2) + (uint32_t)((lane >> 4) * 8) * 2;
    const int brow = (lane & 7) + ((lane >> 4) << 3);
    const int vkey = (lane & 7) + (((lane >> 3) & 1) << 3);
    const uint32_t vcolb = (uint32_t)((lane >> 4) << 3) * 2;

    for (int c = 0; c < 16; c++) {
        if (c + 1 < 16) fill((c + 1) & 1, c + 1);
        if (c + 1 < 16) cp_wait1(); else cp_wait0();
        __syncthreads();

        uint32_t st = sStage + (uint32_t)(c & 1) * 4 * ATILE;
        uint32_t sKh = st, sKl = st + ATILE, sVh = st + 2 * ATILE, sVl = st + 3 * ATILE;

        float s[8][4];
#pragma unroll
        for (int i = 0; i < 8; i++)
#pragma unroll
            for (int j = 0; j < 4; j++) s[i][j] = 0.f;

#pragma unroll
        for (int ks = 0; ks < 8; ks++) {
            const int kc = ks * 16;
            uint32_t ah[4], al[4];
            uint32_t aoff = aoff_base + (uint32_t)kc * 2;
            ldm_x4(ah, sQh + aoff);
            ldm_x4(al, sQl + aoff);
            const uint32_t bcol = (uint32_t)(kc + ((lane >> 3) & 1) * 8) * 2;
#pragma unroll
            for (int np = 0; np < 4; np++) {
                uint32_t bh4[4], bl4[4];
                uint32_t boff = (uint32_t)(np * 16 + brow) * (ARS * 2) + bcol;
                ldm_x4(bh4, sKh + boff);
                ldm_x4(bl4, sKl + boff);
                mma_bf16(s[2 * np],     ah, &bh4[0]);
                mma_bf16(s[2 * np],     ah, &bl4[0]);
                mma_bf16(s[2 * np],     al, &bh4[0]);
                mma_bf16(s[2 * np + 1], ah, &bh4[2]);
                mma_bf16(s[2 * np + 1], ah, &bl4[2]);
                mma_bf16(s[2 * np + 1], al, &bh4[2]);
            }
        }

        float tmax0 = -CUDART_INF_F, tmax1 = -CUDART_INF_F;
#pragma unroll
        for (int nt = 0; nt < 8; nt++) {
            tmax0 = fmaxf(tmax0, fmaxf(s[nt][0], s[nt][1]));
            tmax1 = fmaxf(tmax1, fmaxf(s[nt][2], s[nt][3]));
        }
        tmax0 = fmaxf(tmax0, __shfl_xor_sync(0xffffffffu, tmax0, 1));
        tmax0 = fmaxf(tmax0, __shfl_xor_sync(0xffffffffu, tmax0, 2));
        tmax1 = fmaxf(tmax1, __shfl_xor_sync(0xffffffffu, tmax1, 1));
        tmax1 = fmaxf(tmax1, __shfl_xor_sync(0xffffffffu, tmax1, 2));
        float mn0 = fmaxf(m0, tmax0), mn1 = fmaxf(m1, tmax1);
        float al0 = __expf(m0 - mn0), al1 = __expf(m1 - mn1);
        m0 = mn0; m1 = mn1;
        float ps0 = 0.f, ps1 = 0.f;
#pragma unroll
        for (int nt = 0; nt < 8; nt++) {
            s[nt][0] = __expf(s[nt][0] - mn0);
            s[nt][1] = __expf(s[nt][1] - mn0);
            s[nt][2] = __expf(s[nt][2] - mn1);
            s[nt][3] = __expf(s[nt][3] - mn1);
            ps0 += s[nt][0] + s[nt][1];
            ps1 += s[nt][2] + s[nt][3];
        }
        l0 = l0 * al0 + ps0;
        l1 = l1 * al1 + ps1;
#pragma unroll
        for (int i = 0; i < 16; i++) {
            o[i][0] *= al0; o[i][1] *= al0;
            o[i][2] *= al1; o[i][3] *= al1;
        }

#pragma unroll
        for (int k2 = 0; k2 < 4; k2++) {
            uint32_t aPh[4], aPl[4];
            split2(s[2 * k2][0],     s[2 * k2][1],     aPh[0], aPl[0]);
            split2(s[2 * k2][2],     s[2 * k2][3],     aPh[1], aPl[1]);
            split2(s[2 * k2 + 1][0], s[2 * k2 + 1][1], aPh[2], aPl[2]);
            split2(s[2 * k2 + 1][2], s[2 * k2 + 1][3], aPh[3], aPl[3]);
            const uint32_t vrow = (uint32_t)(k2 * 16 + vkey) * (ARS * 2);
#pragma unroll
            for (int np = 0; np < 8; np++) {
                uint32_t bvh[4], bvl[4];
                uint32_t voff = vrow + (uint32_t)(np * 16) * 2 + vcolb;
                ldm_x4_t(bvh, sVh + voff);
                ldm_x4_t(bvl, sVl + voff);
                mma_bf16(o[2 * np],     aPh, &bvh[0]);
                mma_bf16(o[2 * np],     aPh, &bvl[0]);
                mma_bf16(o[2 * np],     aPl, &bvh[0]);
                mma_bf16(o[2 * np + 1], aPh, &bvh[2]);
                mma_bf16(o[2 * np + 1], aPh, &bvl[2]);
                mma_bf16(o[2 * np + 1], aPl, &bvh[2]);
            }
        }
        __syncthreads();
    }

    l0 += __shfl_xor_sync(0xffffffffu, l0, 1);
    l0 += __shfl_xor_sync(0xffffffffu, l0, 2);
    l1 += __shfl_xor_sync(0xffffffffu, l1, 1);
    l1 += __shfl_xor_sync(0xffffffffu, l1, 2);
    float inv0 = 1.f / l0, inv1 = 1.f / l1;

    const int row0 = q0 + wid * 16 + (lane >> 2);
    const int colb = (lane & 3) * 2;
#pragma unroll
    for (int nt = 0; nt < 16; nt++) {
        int col = nt * 8 + colb;
        size_t i0 = (size_t)(b * Sn + row0) * Cn + h * Dn + col;
        size_t i1 = (size_t)(b * Sn + row0 + 8) * Cn + h * Dn + col;
        uint32_t h0, lo0, h1, lo1;
        split2(o[nt][0] * inv0, o[nt][1] * inv0, h0, lo0);
        split2(o[nt][2] * inv1, o[nt][3] * inv1, h1, lo1);
        *(uint32_t*)&g_oh[i0] = h0;
        *(uint32_t*)&g_ol[i0] = lo0;
        *(uint32_t*)&g_oh[i1] = h1;
        *(uint32_t*)&g_ol[i1] = lo1;
    }
}

// ---------------- launch ----------------------------------------------------
extern "C" void kernel_launch(void* const* d_in, const int* in_sizes, int n_in,
                              void* d_out, int out_size)
{
    const float* x      = (const float*)d_in[0];
    const float* W_qkv  = (const float*)d_in[1];
    const float* q_w    = (const float*)d_in[2];
    const float* k_w    = (const float*)d_in[3];
    const float* W_proj = (const float*)d_in[4];
    const float* b_proj = (const float*)d_in[5];
    const float* fcos   = (const float*)d_in[6];
    const float* fsin   = (const float*)d_in[7];
    float* out = (float*)d_out;

    __nv_bfloat16 *p_xh, *p_xl, *p_oh, *p_ol;
    __nv_bfloat16 *p_wqh, *p_wql, *p_wph, *p_wpl;
    cudaGetSymbolAddress((void**)&p_xh,  g_xh);
    cudaGetSymbolAddress((void**)&p_xl,  g_xl);
    cudaGetSymbolAddress((void**)&p_oh,  g_oh);
    cudaGetSymbolAddress((void**)&p_ol,  g_ol);
    cudaGetSymbolAddress((void**)&p_wqh, g_wqkvT_h);
    cudaGetSymbolAddress((void**)&p_wql, g_wqkvT_l);
    cudaGetSymbolAddress((void**)&p_wph, g_wprojT_h);
    cudaGetSymbolAddress((void**)&p_wpl, g_wprojT_l);

    constexpr int GEMM_SMEM = 2 * STAGE_BYTES;            // 81920 B
    constexpr int ATTN_SMEM = 2 * AQT + 2 * 4 * ATILE;    // 208896 B
    static bool attr_set = false;
    if (!attr_set) {
        cudaFuncSetAttribute(gemm_mma, cudaFuncAttributeMaxDynamicSharedMemorySize, GEMM_SMEM);
        cudaFuncSetAttribute(gemm_qkv_fused, cudaFuncAttributeMaxDynamicSharedMemorySize, GEMM_SMEM);
        cudaFuncSetAttribute(attn_mma, cudaFuncAttributeMaxDynamicSharedMemorySize, ATTN_SMEM);
        attr_set = true;
    }

    // 0) operand conversions
    {
        int n = BSn * Cn;
        split_kernel<<<(n + 255) / 256, 256>>>(x, p_xh, p_xl, n);
        dim3 blk(32, 8);
        transpose_split_kernel<<<dim3(NQKV / 32, Cn / 32), blk>>>(W_qkv, p_wqh, p_wql, Cn, NQKV);
        transpose_split_kernel<<<dim3(Cn / 32, Cn / 32), blk>>>(W_proj, p_wph, p_wpl, Cn, Cn);
    }
    // 1) qkv = x @ W_qkv, fused with rmsnorm + rope + split
    {
        dim3 grid(NQKV / 128, BSn / 128);
        gemm_qkv_fused<<<grid, 256, GEMM_SMEM>>>(p_xh, p_xl, p_wqh, p_wql,
                                                 q_w, k_w, fcos, fsin, Cn);
    }
    // 2) attention (mma.sync)
    {
        dim3 grid(Sn / 128, Bn * Hn);
        attn_mma<<<grid, 256, ATTN_SMEM>>>();
    }
    // 3) out = o @ W_proj + b_proj
    {
        dim3 grid(Cn / 128, BSn / 128);
        gemm_mma<<<grid, 256, GEMM_SMEM>>>(p_oh, p_ol, p_wph, p_wpl, b_proj, out,
                                           BSn, Cn, Cn);
    }
}

// round 15
// speedup vs baseline: 1.3300x; 1.3249x over previous
#include <cuda_runtime.h>
#include <cuda_fp16.h>
#include <math_constants.h>
#include <cstdint>

#define Bn  4
#define Sn  1024
#define Cn  2048
#define Hn  16
#define Dn  128
#define BSn (Bn*Sn)       // 4096
#define NQKV (3*Cn)       // 6144

// ---------------- scratch (device globals; no allocations allowed) ----------
// fp16 operands. A-side operands are hi-only; B-side operands are hi+lo.
__device__ __half g_q [(size_t)Bn*Hn*Sn*Dn];          // q hi (pre-scaled 1/sqrt(D))
__device__ __half g_kh[(size_t)Bn*Hn*Sn*Dn];
__device__ __half g_kl[(size_t)Bn*Hn*Sn*Dn];
__device__ __half g_vh[(size_t)Bn*Hn*Sn*Dn];
__device__ __half g_vl[(size_t)Bn*Hn*Sn*Dn];

__device__ __half g_x [(size_t)BSn*Cn];               // x hi
__device__ __half g_o [(size_t)BSn*Cn];               // attention out hi
__device__ __half g_wqkvT_h[(size_t)NQKV*Cn];         // [N,K]
__device__ __half g_wqkvT_l[(size_t)NQKV*Cn];
__device__ __half g_wprojT_h[(size_t)Cn*Cn];
__device__ __half g_wprojT_l[(size_t)Cn*Cn];

// =================== helpers ================================================
__device__ __forceinline__ uint32_t smem_to_u32(const void* p) {
    uint32_t a;
    asm("{ .reg .u64 t; cvta.to.shared.u64 t, %1; cvt.u32.u64 %0, t; }"
        : "=r"(a) : "l"(p));
    return a;
}
__device__ __forceinline__ void cp16(uint32_t dst, const void* src) {
    asm volatile("cp.async.cg.shared.global [%0], [%1], 16;" :: "r"(dst), "l"(src));
}
__device__ __forceinline__ void cp_commit() { asm volatile("cp.async.commit_group;"); }
__device__ __forceinline__ void cp_wait1()  { asm volatile("cp.async.wait_group 1;" ::: "memory"); }
__device__ __forceinline__ void cp_wait0()  { asm volatile("cp.async.wait_group 0;" ::: "memory"); }

__device__ __forceinline__ void ldm_x4(uint32_t* r, uint32_t addr) {
    asm volatile("ldmatrix.sync.aligned.m8n8.x4.shared.b16 {%0,%1,%2,%3}, [%4];"
        : "=r"(r[0]), "=r"(r[1]), "=r"(r[2]), "=r"(r[3]) : "r"(addr));
}
__device__ __forceinline__ void ldm_x4_t(uint32_t* r, uint32_t addr) {
    asm volatile("ldmatrix.sync.aligned.m8n8.x4.trans.shared.b16 {%0,%1,%2,%3}, [%4];"
        : "=r"(r[0]), "=r"(r[1]), "=r"(r[2]), "=r"(r[3]) : "r"(addr));
}
__device__ __forceinline__ void mma_f16(float* d, const uint32_t* a, const uint32_t* b) {
    asm volatile(
        "mma.sync.aligned.m16n8k16.row.col.f32.f16.f16.f32 "
        "{%0,%1,%2,%3}, {%4,%5,%6,%7}, {%8,%9}, {%0,%1,%2,%3};"
        : "+f"(d[0]), "+f"(d[1]), "+f"(d[2]), "+f"(d[3])
        : "r"(a[0]), "r"(a[1]), "r"(a[2]), "r"(a[3]), "r"(b[0]), "r"(b[1]));
}
__device__ __forceinline__ uint32_t pack2h(float e0, float e1) {
    __half2 t = __floats2half2_rn(e0, e1);
    return *(uint32_t*)&t;
}
__device__ __forceinline__ void split2h(float e0, float e1, uint32_t& hi, uint32_t& lo) {
    __half h0 = __float2half_rn(e0), h1 = __float2half_rn(e1);
    __half2 hp = __halves2half2(h0, h1);
    hi = *(uint32_t*)&hp;
    lo = pack2h(e0 - __half2float(h0), e1 - __half2float(h1));
}

// ---------------- shared GEMM mainloop (fp16 2-term) -------------------------
// C = A @ B^T where A is fp16 hi-only, B supplied as hi+lo fp16 [N,K].
#define RS 40
#define ARRB (128 * RS * 2)              // one array block: 10240 B
#define STAGE_BYTES (3 * ARRB)           // A, Bh, Bl = 30720 B

#define GEMM_FILL(stage, k0)                                                     \
    do {                                                                         \
        uint32_t sbf = sbase + (uint32_t)(stage) * STAGE_BYTES;                  \
        cp16(sbf + fso,             A  + offA + (k0));                           \
        cp16(sbf + fso2,            A  + offA + (size_t)64 * K + (k0));          \
        cp16(sbf + ARRB + fso,      Bh + offB + (k0));                           \
        cp16(sbf + ARRB + fso2,     Bh + offB + (size_t)64 * K + (k0));          \
        cp16(sbf + 2 * ARRB + fso,  Bl + offB + (k0));                           \
        cp16(sbf + 2 * ARRB + fso2, Bl + offB + (size_t)64 * K + (k0));          \
        cp_commit();                                                             \
    } while (0)

#define GEMM_LDSM(ks, AH, BH, BL)                                                \
    do {                                                                         \
        const int kc = (ks) * 16;                                                \
        _Pragma("unroll")                                                        \
        for (int mt = 0; mt < 4; mt++) {                                         \
            uint32_t roff = (uint32_t)(warp_m * 64 + mt * 16 + lm) * (RS * 2)    \
                          + (uint32_t)(kc + lk8 * 8) * 2;                        \
            ldm_x4(AH[mt], sA + roff);                                           \
        }                                                                        \
        _Pragma("unroll")                                                        \
        for (int ntp = 0; ntp < 2; ntp++) {                                      \
            uint32_t roff = (uint32_t)(warp_n * 32 + ntp * 16 + brw) * (RS * 2)  \
                          + (uint32_t)(kc + bkh * 8) * 2;                        \
            ldm_x4(BH[ntp], sBh + roff);                                         \
            ldm_x4(BL[ntp], sBl + roff);                                         \
        }                                                                        \
    } while (0)

#define GEMM_MMAS(AH, BH, BL)                                                    \
    do {                                                                         \
        _Pragma("unroll")                                                        \
        for (int ntp = 0; ntp < 2; ntp++)                                        \
            _Pragma("unroll")                                                    \
            for (int mt = 0; mt < 4; mt++) {                                     \
                mma_f16(acc[mt][2 * ntp],     AH[mt], &BH[ntp][0]);              \
                mma_f16(acc[mt][2 * ntp],     AH[mt], &BL[ntp][0]);              \
                mma_f16(acc[mt][2 * ntp + 1], AH[mt], &BH[ntp][2]);              \
                mma_f16(acc[mt][2 * ntp + 1], AH[mt], &BL[ntp][2]);              \
            }                                                                    \
    } while (0)

#define GEMM_MAINLOOP(NCexpr)                                                    \
    const int NC = (NCexpr);                                                     \
    const int lm   = lane & 15;                                                  \
    const int lk8  = lane >> 4;                                                  \
    const int brw  = (lane & 7) + ((lane >> 4) << 3);                            \
    const int bkh  = (lane >> 3) & 1;                                            \
    const int fr   = tid >> 2;                                                   \
    const int fch  = tid & 3;                                                    \
    const size_t offA = (size_t)(row0 + fr) * K + fch * 8;                       \
    const size_t offB = (size_t)(col0 + fr) * K + fch * 8;                       \
    const uint32_t fso  = (uint32_t)fr * (RS * 2) + (uint32_t)fch * 16;          \
    const uint32_t fso2 = fso + 64u * (RS * 2);                                  \
    GEMM_FILL(0, 0);                                                             \
    for (int c = 0; c < NC; c++) {                                               \
        if (c + 1 < NC) GEMM_FILL((c + 1) & 1, (c + 1) << 5);                    \
        if (c + 1 < NC) cp_wait1(); else cp_wait0();                             \
        __syncthreads();                                                         \
        uint32_t sbf = sbase + (uint32_t)(c & 1) * STAGE_BYTES;                  \
        uint32_t sA  = sbf;                                                      \
        uint32_t sBh = sbf + ARRB;                                               \
        uint32_t sBl = sbf + 2 * ARRB;                                           \
        {                                                                        \
            uint32_t ah0[4][4], bh0[2][4], bl0[2][4];                            \
            GEMM_LDSM(0, ah0, bh0, bl0);                                         \
            GEMM_MMAS(ah0, bh0, bl0);                                            \
        }                                                                        \
        {                                                                        \
            uint32_t ah1[4][4], bh1[2][4], bl1[2][4];                            \
            GEMM_LDSM(1, ah1, bh1, bl1);                                         \
            __syncthreads();                                                     \
            GEMM_MMAS(ah1, bh1, bl1);                                            \
        }                                                                        \
    }

// ---------------- plain GEMM (proj): fp32 out + bias -------------------------
__global__ __launch_bounds__(256, 2) void gemm_mma(
    const __half* __restrict__ A,
    const __half* __restrict__ Bh, const __half* __restrict__ Bl,
    const float* __restrict__ bias, float* __restrict__ C,
    int M, int N, int K)
{
    extern __shared__ char dsm[];
    const uint32_t sbase = smem_to_u32(dsm);
    const int tid = threadIdx.x;
    const int wid = tid >> 5, lane = tid & 31;
    const int warp_m = wid >> 2;
    const int warp_n = wid & 3;
    const int row0 = blockIdx.y * 128;
    const int col0 = blockIdx.x * 128;

    float acc[4][4][4];
#pragma unroll
    for (int i = 0; i < 4; i++)
#pragma unroll
        for (int j = 0; j < 4; j++)
#pragma unroll
            for (int q = 0; q < 4; q++) acc[i][j][q] = 0.f;

    GEMM_MAINLOOP(K >> 5)

    const int qr = lane >> 2;
    const int qc = (lane & 3) * 2;
#pragma unroll
    for (int mt = 0; mt < 4; mt++) {
#pragma unroll
        for (int nt = 0; nt < 4; nt++) {
            int col = col0 + warp_n * 32 + nt * 8 + qc;
            float b0 = bias[col], b1 = bias[col + 1];
            int r0 = row0 + warp_m * 64 + mt * 16 + qr;
            float2 v0 = { acc[mt][nt][0] + b0, acc[mt][nt][1] + b1 };
            float2 v1 = { acc[mt][nt][2] + b0, acc[mt][nt][3] + b1 };
            *(float2*)&C[(size_t)r0 * N + col] = v0;
            *(float2*)&C[(size_t)(r0 + 8) * N + col] = v1;
        }
    }
}

// ---------------- fused QKV GEMM: + RMSNorm + RoPE + fp16 outputs ------------
// grid (48, 32): blockIdx.x = type*16 + head.
__global__ __launch_bounds__(256, 2) void gemm_qkv_fused(
    const __half* __restrict__ A,
    const __half* __restrict__ Bh, const __half* __restrict__ Bl,
    const float* __restrict__ qw, const float* __restrict__ kw,
    const float* __restrict__ fcos, const float* __restrict__ fsin,
    int K)
{
    extern __shared__ char dsm[];
    const uint32_t sbase = smem_to_u32(dsm);
    const int tid = threadIdx.x;
    const int wid = tid >> 5, lane = tid & 31;
    const int warp_m = wid >> 2;
    const int warp_n = wid & 3;
    const int row0 = blockIdx.y * 128;
    const int col0 = blockIdx.x * 128;

    float acc[4][4][4];
#pragma unroll
    for (int i = 0; i < 4; i++)
#pragma unroll
        for (int j = 0; j < 4; j++)
#pragma unroll
            for (int q = 0; q < 4; q++) acc[i][j][q] = 0.f;

    GEMM_MAINLOOP(K >> 5)

    // ---- fused epilogue ----
    const int t  = blockIdx.x >> 4;     // 0=q, 1=k, 2=v
    const int hh = blockIdx.x & 15;
    const int qr = lane >> 2;
    const int qc = (lane & 3) * 2;

    __syncthreads();                    // MMA block done in all warps
    float* red = (float*)dsm;           // [128][4]

    float rstd[8];
#pragma unroll
    for (int j = 0; j < 8; j++) rstd[j] = 1.f;

    if (t < 2) {
#pragma unroll
        for (int mt = 0; mt < 4; mt++) {
#pragma unroll
            for (int half = 0; half < 2; half++) {
                float ss = 0.f;
#pragma unroll
                for (int nt = 0; nt < 4; nt++) {
                    float e = acc[mt][nt][half * 2], o_ = acc[mt][nt][half * 2 + 1];
                    ss += e * e + o_ * o_;
                }
                ss += __shfl_xor_sync(0xffffffffu, ss, 1);
                ss += __shfl_xor_sync(0xffffffffu, ss, 2);
                if ((lane & 3) == 0)
                    red[(warp_m * 64 + mt * 16 + half * 8 + qr) * 4 + warp_n] = ss;
            }
        }
        __syncthreads();
#pragma unroll
        for (int mt = 0; mt < 4; mt++)
#pragma unroll
            for (int half = 0; half < 2; half++) {
                int rl = warp_m * 64 + mt * 16 + half * 8 + qr;
                float tot = red[rl * 4] + red[rl * 4 + 1] + red[rl * 4 + 2] + red[rl * 4 + 3];
                rstd[mt * 2 + half] = rsqrtf(tot * (1.0f / Dn) + 1e-6f);
            }
    }

    const float* wnorm = (t == 0) ? qw : kw;
    const float tsc = (t == 0) ? 0.08838834764831845f : 1.0f;

#pragma unroll
    for (int mt = 0; mt < 4; mt++) {
#pragma unroll
        for (int half = 0; half < 2; half++) {
            int srow = row0 + warp_m * 64 + mt * 16 + half * 8 + qr;   // bs
            int b = srow >> 10, s = srow & 1023;
            size_t obase = ((size_t)(b * Hn + hh) * Sn + s) * Dn;
            float r = rstd[mt * 2 + half];
#pragma unroll
            for (int nt = 0; nt < 4; nt++) {
                int d0 = warp_n * 32 + nt * 8 + qc;
                float e  = acc[mt][nt][half * 2];
                float o_ = acc[mt][nt][half * 2 + 1];
                if (t == 0) {
                    e  = e  * r * wnorm[d0];
                    o_ = o_ * r * wnorm[d0 + 1];
                    float cs = fcos[(size_t)srow * (Dn / 2) + (d0 >> 1)];
                    float sn = fsin[(size_t)srow * (Dn / 2) + (d0 >> 1)];
                    float re = (e * cs - o_ * sn) * tsc;
                    float im = (e * sn + o_ * cs) * tsc;
                    *(uint32_t*)&g_q[obase + d0] = pack2h(re, im);
                } else if (t == 1) {
                    e  = e  * r * wnorm[d0];
                    o_ = o_ * r * wnorm[d0 + 1];
                    float cs = fcos[(size_t)srow * (Dn / 2) + (d0 >> 1)];
                    float sn = fsin[(size_t)srow * (Dn / 2) + (d0 >> 1)];
                    float re = e * cs - o_ * sn;
                    float im = e * sn + o_ * cs;
                    uint32_t hiw, low;
                    split2h(re, im, hiw, low);
                    *(uint32_t*)&g_kh[obase + d0] = hiw;
                    *(uint32_t*)&g_kl[obase + d0] = low;
                } else {
                    uint32_t hiw, low;
                    split2h(e, o_, hiw, low);
                    *(uint32_t*)&g_vh[obase + d0] = hiw;
                    *(uint32_t*)&g_vl[obase + d0] = low;
                }
            }
        }
    }
}

// ---------------- fp32 -> fp16 convert, elementwise --------------------------
__global__ __launch_bounds__(256) void cvt_kernel(
    const float* __restrict__ in, __half* __restrict__ out, int n)
{
    int i = blockIdx.x * blockDim.x + threadIdx.x;
    if (i < n) out[i] = __float2half_rn(in[i]);
}

// ---------------- transpose + split: W[K,N] -> T[N,K] hi/lo fp16 -------------
__global__ __launch_bounds__(256) void transpose_split_kernel(
    const float* __restrict__ W, __half* __restrict__ Th,
    __half* __restrict__ Tl, int K, int N)
{
    __shared__ float t[32][33];
    int tx = threadIdx.x, ty = threadIdx.y;
    int n0 = blockIdx.x * 32, k0 = blockIdx.y * 32;
#pragma unroll
    for (int i = ty; i < 32; i += 8)
        t[i][tx] = W[(size_t)(k0 + i) * N + n0 + tx];
    __syncthreads();
#pragma unroll
    for (int i = ty; i < 32; i += 8) {
        float v = t[tx][i];
        __half h = __float2half_rn(v);
        float r = v - __half2float(h);
        size_t o = (size_t)(n0 + i) * K + k0 + tx;
        Th[o] = h;
        Tl[o] = __float2half_rn(r);
    }
}

// ---------------- flash attention, fp16 2-term -------------------------------
#define ARS   136                    // smem row stride (fp16 elems) = 272 B
#define ATILE (64 * ARS * 2)         // 17408
#define AQT   (128 * ARS * 2)        // 34816

__global__ __launch_bounds__(256) void attn_mma()
{
    extern __shared__ char asmem[];
    const uint32_t sb = smem_to_u32(asmem);
    const uint32_t sQ = sb;
    const uint32_t sStage = sb + AQT;   // + stage*4*ATILE: kh,kl,vh,vl

    const int tid = threadIdx.x;
    const int wid = tid >> 5, lane = tid & 31;
    const int bh = blockIdx.y;
    const int q0 = blockIdx.x * 128;
    const int b = bh / Hn, h = bh % Hn;

    const __half* qg = g_q  + (size_t)bh * Sn * Dn;
    const __half* kh = g_kh + (size_t)bh * Sn * Dn;
    const __half* kl = g_kl + (size_t)bh * Sn * Dn;
    const __half* vh = g_vh + (size_t)bh * Sn * Dn;
    const __half* vl = g_vl + (size_t)bh * Sn * Dn;

    // q tile: 128 rows x 16 chunks = 2048 cp16
#pragma unroll
    for (int it = 0; it < 8; it++) {
        int idx = tid + it * 256;
        int r = idx >> 4, ch = idx & 15;
        cp16(sQ + (uint32_t)r * (ARS * 2) + (uint32_t)ch * 16,
             qg + (size_t)(q0 + r) * Dn + ch * 8);
    }

    auto fill = [&](int stage, int c) {
        uint32_t base = sStage + (uint32_t)stage * 4 * ATILE;
        int k0 = c * 64;
#pragma unroll
        for (int it = 0; it < 16; it++) {
            int idx = tid + it * 256;
            int arr = idx >> 10;
            int rem = idx & 1023;
            int r = rem >> 4, ch = rem & 15;
            const __half* s =
                (arr == 0 ? kh : arr == 1 ? kl : arr == 2 ? vh : vl)
                + (size_t)(k0 + r) * Dn + ch * 8;
            cp16(base + (uint32_t)arr * ATILE + (uint32_t)r * (ARS * 2) + (uint32_t)ch * 16, s);
        }
        cp_commit();
    };

    fill(0, 0);   // group also contains q loads

    float o[16][4];
#pragma unroll
    for (int i = 0; i < 16; i++)
#pragma unroll
        for (int j = 0; j < 4; j++) o[i][j] = 0.f;
    float m0 = -CUDART_INF_F, m1 = -CUDART_INF_F, l0 = 0.f, l1 = 0.f;

    const int arow = wid * 16 + (lane & 15);
    const uint32_t aoff_base = (uint32_t)arow * (ARS * 2) + (uint32_t)((lane >> 4) * 8) * 2;
    const int brow = (lane & 7) + ((lane >> 4) << 3);
    const int vkey = (lane & 7) + (((lane >> 3) & 1) << 3);
    const uint32_t vcolb = (uint32_t)((lane >> 4) << 3) * 2;

    for (int c = 0; c < 16; c++) {
        if (c + 1 < 16) fill((c + 1) & 1, c + 1);
        if (c + 1 < 16) cp_wait1(); else cp_wait0();
        __syncthreads();

        uint32_t st = sStage + (uint32_t)(c & 1) * 4 * ATILE;
        uint32_t sKh = st, sKl = st + ATILE, sVh = st + 2 * ATILE, sVl = st + 3 * ATILE;

        float s[8][4];
#pragma unroll
        for (int i = 0; i < 8; i++)
#pragma unroll
            for (int j = 0; j < 4; j++) s[i][j] = 0.f;

#pragma unroll
        for (int ks = 0; ks < 8; ks++) {
            const int kc = ks * 16;
            uint32_t ah[4];
            ldm_x4(ah, sQ + aoff_base + (uint32_t)kc * 2);
            const uint32_t bcol = (uint32_t)(kc + ((lane >> 3) & 1) * 8) * 2;
#pragma unroll
            for (int np = 0; np < 4; np++) {
                uint32_t bh4[4], bl4[4];
                uint32_t boff = (uint32_t)(np * 16 + brow) * (ARS * 2) + bcol;
                ldm_x4(bh4, sKh + boff);
                ldm_x4(bl4, sKl + boff);
                mma_f16(s[2 * np],     ah, &bh4[0]);
                mma_f16(s[2 * np],     ah, &bl4[0]);
                mma_f16(s[2 * np + 1], ah, &bh4[2]);
                mma_f16(s[2 * np + 1], ah, &bl4[2]);
            }
        }

        float tmax0 = -CUDART_INF_F, tmax1 = -CUDART_INF_F;
#pragma unroll
        for (int nt = 0; nt < 8; nt++) {
            tmax0 = fmaxf(tmax0, fmaxf(s[nt][0], s[nt][1]));
            tmax1 = fmaxf(tmax1, fmaxf(s[nt][2], s[nt][3]));
        }
        tmax0 = fmaxf(tmax0, __shfl_xor_sync(0xffffffffu, tmax0, 1));
        tmax0 = fmaxf(tmax0, __shfl_xor_sync(0xffffffffu, tmax0, 2));
        tmax1 = fmaxf(tmax1, __shfl_xor_sync(0xffffffffu, tmax1, 1));
        tmax1 = fmaxf(tmax1, __shfl_xor_sync(0xffffffffu, tmax1, 2));
        float mn0 = fmaxf(m0, tmax0), mn1 = fmaxf(m1, tmax1);
        float al0 = __expf(m0 - mn0), al1 = __expf(m1 - mn1);
        m0 = mn0; m1 = mn1;
        float ps0 = 0.f, ps1 = 0.f;
#pragma unroll
        for (int nt = 0; nt < 8; nt++) {
            s[nt][0] = __expf(s[nt][0] - mn0);
            s[nt][1] = __expf(s[nt][1] - mn0);
            s[nt][2] = __expf(s[nt][2] - mn1);
            s[nt][3] = __expf(s[nt][3] - mn1);
            ps0 += s[nt][0] + s[nt][1];
            ps1 += s[nt][2] + s[nt][3];
        }
        l0 = l0 * al0 + ps0;
        l1 = l1 * al1 + ps1;
#pragma unroll
        for (int i = 0; i < 16; i++) {
            o[i][0] *= al0; o[i][1] *= al0;
            o[i][2] *= al1; o[i][3] *= al1;
        }

#pragma unroll
        for (int k2 = 0; k2 < 4; k2++) {
            uint32_t aP[4];
            aP[0] = pack2h(s[2 * k2][0],     s[2 * k2][1]);
            aP[1] = pack2h(s[2 * k2][2],     s[2 * k2][3]);
            aP[2] = pack2h(s[2 * k2 + 1][0], s[2 * k2 + 1][1]);
            aP[3] = pack2h(s[2 * k2 + 1][2], s[2 * k2 + 1][3]);
            const uint32_t vrow = (uint32_t)(k2 * 16 + vkey) * (ARS * 2);
#pragma unroll
            for (int np = 0; np < 8; np++) {
                uint32_t bvh[4], bvl[4];
                uint32_t voff = vrow + (uint32_t)(np * 16) * 2 + vcolb;
                ldm_x4_t(bvh, sVh + voff);
                ldm_x4_t(bvl, sVl + voff);
                mma_f16(o[2 * np],     aP, &bvh[0]);
                mma_f16(o[2 * np],     aP, &bvl[0]);
                mma_f16(o[2 * np + 1], aP, &bvh[2]);
                mma_f16(o[2 * np + 1], aP, &bvl[2]);
            }
        }
        __syncthreads();
    }

    l0 += __shfl_xor_sync(0xffffffffu, l0, 1);
    l0 += __shfl_xor_sync(0xffffffffu, l0, 2);
    l1 += __shfl_xor_sync(0xffffffffu, l1, 1);
    l1 += __shfl_xor_sync(0xffffffffu, l1, 2);
    float inv0 = 1.f / l0, inv1 = 1.f / l1;

    const int row0 = q0 + wid * 16 + (lane >> 2);
    const int colb = (lane & 3) * 2;
#pragma unroll
    for (int nt = 0; nt < 16; nt++) {
        int col = nt * 8 + colb;
        size_t i0 = (size_t)(b * Sn + row0) * Cn + h * Dn + col;
        size_t i1 = (size_t)(b * Sn + row0 + 8) * Cn + h * Dn + col;
        *(uint32_t*)&g_o[i0] = pack2h(o[nt][0] * inv0, o[nt][1] * inv0);
        *(uint32_t*)&g_o[i1] = pack2h(o[nt][2] * inv1, o[nt][3] * inv1);
    }
}

// ---------------- launch ----------------------------------------------------
extern "C" void kernel_launch(void* const* d_in, const int* in_sizes, int n_in,
                              void* d_out, int out_size)
{
    const float* x      = (const float*)d_in[0];
    const float* W_qkv  = (const float*)d_in[1];
    const float* q_w    = (const float*)d_in[2];
    const float* k_w    = (const float*)d_in[3];
    const float* W_proj = (const float*)d_in[4];
    const float* b_proj = (const float*)d_in[5];
    const float* fcos   = (const float*)d_in[6];
    const float* fsin   = (const float*)d_in[7];
    float* out = (float*)d_out;

    __half *p_x, *p_o, *p_wqh, *p_wql, *p_wph, *p_wpl;
    cudaGetSymbolAddress((void**)&p_x,   g_x);
    cudaGetSymbolAddress((void**)&p_o,   g_o);
    cudaGetSymbolAddress((void**)&p_wqh, g_wqkvT_h);
    cudaGetSymbolAddress((void**)&p_wql, g_wqkvT_l);
    cudaGetSymbolAddress((void**)&p_wph, g_wprojT_h);
    cudaGetSymbolAddress((void**)&p_wpl, g_wprojT_l);

    constexpr int GEMM_SMEM = 2 * STAGE_BYTES;            // 61440 B
    constexpr int ATTN_SMEM = AQT + 2 * 4 * ATILE;        // 174080 B
    static bool attr_set = false;
    if (!attr_set) {
        cudaFuncSetAttribute(gemm_mma, cudaFuncAttributeMaxDynamicSharedMemorySize, GEMM_SMEM);
        cudaFuncSetAttribute(gemm_qkv_fused, cudaFuncAttributeMaxDynamicSharedMemorySize, GEMM_SMEM);
        cudaFuncSetAttribute(attn_mma, cudaFuncAttributeMaxDynamicSharedMemorySize, ATTN_SMEM);
        attr_set = true;
    }

    // 0) operand conversions
    {
        int n = BSn * Cn;
        cvt_kernel<<<(n + 255) / 256, 256>>>(x, p_x, n);
        dim3 blk(32, 8);
        transpose_split_kernel<<<dim3(NQKV / 32, Cn / 32), blk>>>(W_qkv, p_wqh, p_wql, Cn, NQKV);
        transpose_split_kernel<<<dim3(Cn / 32, Cn / 32), blk>>>(W_proj, p_wph, p_wpl, Cn, Cn);
    }
    // 1) qkv = x @ W_qkv, fused with rmsnorm + rope
    {
        dim3 grid(NQKV / 128, BSn / 128);
        gemm_qkv_fused<<<grid, 256, GEMM_SMEM>>>(p_x, p_wqh, p_wql,
                                                 q_w, k_w, fcos, fsin, Cn);
    }
    // 2) attention (mma.sync fp16)
    {
        dim3 grid(Sn / 128, Bn * Hn);
        attn_mma<<<grid, 256, ATTN_SMEM>>>();
    }
    // 3) out = o @ W_proj + b_proj
    {
        dim3 grid(Cn / 128, BSn / 128);
        gemm_mma<<<grid, 256, GEMM_SMEM>>>(p_o, p_wph, p_wpl, b_proj, out,
                                           BSn, Cn, Cn);
    }
}

// round 16
// speedup vs baseline: 1.3436x; 1.0102x over previous
#include <cuda_runtime.h>
#include <cuda_fp16.h>
#include <math_constants.h>
#include <cstdint>

#define Bn  4
#define Sn  1024
#define Cn  2048
#define Hn  16
#define Dn  128
#define BSn (Bn*Sn)       // 4096
#define NQKV (3*Cn)       // 6144

// ---------------- scratch (device globals; no allocations allowed) ----------
__device__ __half g_q [(size_t)Bn*Hn*Sn*Dn];          // q hi (pre-scaled 1/sqrt(D))
__device__ __half g_kh[(size_t)Bn*Hn*Sn*Dn];
__device__ __half g_kl[(size_t)Bn*Hn*Sn*Dn];
__device__ __half g_vh[(size_t)Bn*Hn*Sn*Dn];
__device__ __half g_vl[(size_t)Bn*Hn*Sn*Dn];

__device__ __half g_x [(size_t)BSn*Cn];               // x hi
__device__ __half g_o [(size_t)BSn*Cn];               // attention out hi
__device__ __half g_wqkvT_h[(size_t)NQKV*Cn];         // [N,K]
__device__ __half g_wqkvT_l[(size_t)NQKV*Cn];
__device__ __half g_wprojT_h[(size_t)Cn*Cn];
__device__ __half g_wprojT_l[(size_t)Cn*Cn];

// =================== helpers ================================================
__device__ __forceinline__ uint32_t smem_to_u32(const void* p) {
    uint32_t a;
    asm("{ .reg .u64 t; cvta.to.shared.u64 t, %1; cvt.u32.u64 %0, t; }"
        : "=r"(a) : "l"(p));
    return a;
}
__device__ __forceinline__ void cp16(uint32_t dst, const void* src) {
    asm volatile("cp.async.cg.shared.global [%0], [%1], 16;" :: "r"(dst), "l"(src));
}
__device__ __forceinline__ void cp_commit() { asm volatile("cp.async.commit_group;"); }
__device__ __forceinline__ void cp_wait1()  { asm volatile("cp.async.wait_group 1;" ::: "memory"); }
__device__ __forceinline__ void cp_wait0()  { asm volatile("cp.async.wait_group 0;" ::: "memory"); }

__device__ __forceinline__ void ldm_x4(uint32_t* r, uint32_t addr) {
    asm volatile("ldmatrix.sync.aligned.m8n8.x4.shared.b16 {%0,%1,%2,%3}, [%4];"
        : "=r"(r[0]), "=r"(r[1]), "=r"(r[2]), "=r"(r[3]) : "r"(addr));
}
__device__ __forceinline__ void ldm_x4_t(uint32_t* r, uint32_t addr) {
    asm volatile("ldmatrix.sync.aligned.m8n8.x4.trans.shared.b16 {%0,%1,%2,%3}, [%4];"
        : "=r"(r[0]), "=r"(r[1]), "=r"(r[2]), "=r"(r[3]) : "r"(addr));
}
__device__ __forceinline__ void mma_f16(float* d, const uint32_t* a, const uint32_t* b) {
    asm volatile(
        "mma.sync.aligned.m16n8k16.row.col.f32.f16.f16.f32 "
        "{%0,%1,%2,%3}, {%4,%5,%6,%7}, {%8,%9}, {%0,%1,%2,%3};"
        : "+f"(d[0]), "+f"(d[1]), "+f"(d[2]), "+f"(d[3])
        : "r"(a[0]), "r"(a[1]), "r"(a[2]), "r"(a[3]), "r"(b[0]), "r"(b[1]));
}
__device__ __forceinline__ uint32_t pack2h(float e0, float e1) {
    __half2 t = __floats2half2_rn(e0, e1);
    return *(uint32_t*)&t;
}
__device__ __forceinline__ void split2h(float e0, float e1, uint32_t& hi, uint32_t& lo) {
    __half h0 = __float2half_rn(e0), h1 = __float2half_rn(e1);
    __half2 hp = __halves2half2(h0, h1);
    hi = *(uint32_t*)&hp;
    lo = pack2h(e0 - __half2float(h0), e1 - __half2float(h1));
}

// ---------------- shared GEMM mainloop (fp16 2-term, BK=64) ------------------
// C = A @ B^T where A is fp16 hi-only, B supplied as hi+lo fp16 [N,K].
#define RSB 144                          // row stride bytes (64 fp16 + 8 pad)
#define ARRB (128 * RSB)                 // one array block: 18432 B
#define STAGE_BYTES (3 * ARRB)           // A, Bh, Bl = 55296 B

#define GEMM_FILL(stage, k0)                                                     \
    do {                                                                         \
        uint32_t sbf = sbase + (uint32_t)(stage) * STAGE_BYTES;                  \
        cp16(sbf + fso,                  A  + offA + (k0));                      \
        cp16(sbf + fso + 64,             A  + offA + (k0) + 32);                 \
        cp16(sbf + fso2,                 A  + offA64 + (k0));                    \
        cp16(sbf + fso2 + 64,            A  + offA64 + (k0) + 32);               \
        cp16(sbf + ARRB + fso,           Bh + offB + (k0));                      \
        cp16(sbf + ARRB + fso + 64,      Bh + offB + (k0) + 32);                 \
        cp16(sbf + ARRB + fso2,          Bh + offB64 + (k0));                    \
        cp16(sbf + ARRB + fso2 + 64,     Bh + offB64 + (k0) + 32);               \
        cp16(sbf + 2 * ARRB + fso,       Bl + offB + (k0));                      \
        cp16(sbf + 2 * ARRB + fso + 64,  Bl + offB + (k0) + 32);                 \
        cp16(sbf + 2 * ARRB + fso2,      Bl + offB64 + (k0));                    \
        cp16(sbf + 2 * ARRB + fso2 + 64, Bl + offB64 + (k0) + 32);               \
        cp_commit();                                                             \
    } while (0)

#define GEMM_LDSM(ks, AH, BH, BL)                                                \
    do {                                                                         \
        const int kc = (ks) * 16;                                                \
        _Pragma("unroll")                                                        \
        for (int mt = 0; mt < 4; mt++) {                                         \
            uint32_t roff = (uint32_t)(warp_m * 64 + mt * 16 + lm) * RSB         \
                          + (uint32_t)(kc + lk8 * 8) * 2;                        \
            ldm_x4(AH[mt], sA + roff);                                           \
        }                                                                        \
        _Pragma("unroll")                                                        \
        for (int ntp = 0; ntp < 2; ntp++) {                                      \
            uint32_t roff = (uint32_t)(warp_n * 32 + ntp * 16 + brw) * RSB       \
                          + (uint32_t)(kc + bkh * 8) * 2;                        \
            ldm_x4(BH[ntp], sBh + roff);                                         \
            ldm_x4(BL[ntp], sBl + roff);                                         \
        }                                                                        \
    } while (0)

#define GEMM_MMAS(AH, BH, BL)                                                    \
    do {                                                                         \
        _Pragma("unroll")                                                        \
        for (int ntp = 0; ntp < 2; ntp++)                                        \
            _Pragma("unroll")                                                    \
            for (int mt = 0; mt < 4; mt++) {                                     \
                mma_f16(acc[mt][2 * ntp],     AH[mt], &BH[ntp][0]);              \
                mma_f16(acc[mt][2 * ntp],     AH[mt], &BL[ntp][0]);              \
                mma_f16(acc[mt][2 * ntp + 1], AH[mt], &BH[ntp][2]);              \
                mma_f16(acc[mt][2 * ntp + 1], AH[mt], &BL[ntp][2]);              \
            }                                                                    \
    } while (0)

// fill(c+1); wait1; sync; [LDSM(ks)->MMA(ks)]x4 with WAR-guard sync after the
// LAST LDSM (before MMA(3)) so the tail MMA block absorbs the barrier.
#define GEMM_MAINLOOP(NCexpr)                                                    \
    const int NC = (NCexpr);                                                     \
    const int lm   = lane & 15;                                                  \
    const int lk8  = lane >> 4;                                                  \
    const int brw  = (lane & 7) + ((lane >> 4) << 3);                            \
    const int bkh  = (lane >> 3) & 1;                                            \
    const int fr   = tid >> 2;                                                   \
    const int fch  = tid & 3;                                                    \
    const size_t offA   = (size_t)(row0 + fr) * K + fch * 8;                     \
    const size_t offA64 = offA + (size_t)64 * K;                                 \
    const size_t offB   = (size_t)(col0 + fr) * K + fch * 8;                     \
    const size_t offB64 = offB + (size_t)64 * K;                                 \
    const uint32_t fso  = (uint32_t)fr * RSB + (uint32_t)fch * 16;               \
    const uint32_t fso2 = fso + 64u * RSB;                                       \
    GEMM_FILL(0, 0);                                                             \
    for (int c = 0; c < NC; c++) {                                               \
        if (c + 1 < NC) GEMM_FILL((c + 1) & 1, (c + 1) << 6);                    \
        if (c + 1 < NC) cp_wait1(); else cp_wait0();                             \
        __syncthreads();                                                         \
        uint32_t sbf = sbase + (uint32_t)(c & 1) * STAGE_BYTES;                  \
        uint32_t sA  = sbf;                                                      \
        uint32_t sBh = sbf + ARRB;                                               \
        uint32_t sBl = sbf + 2 * ARRB;                                           \
        _Pragma("unroll")                                                        \
        for (int ks = 0; ks < 4; ks++) {                                         \
            uint32_t ah[4][4], bh[2][4], bl[2][4];                               \
            GEMM_LDSM(ks, ah, bh, bl);                                           \
            if (ks == 3) __syncthreads();                                        \
            GEMM_MMAS(ah, bh, bl);                                               \
        }                                                                        \
    }

// ---------------- plain GEMM (proj): fp32 out + bias -------------------------
__global__ __launch_bounds__(256, 2) void gemm_mma(
    const __half* __restrict__ A,
    const __half* __restrict__ Bh, const __half* __restrict__ Bl,
    const float* __restrict__ bias, float* __restrict__ C,
    int M, int N, int K)
{
    extern __shared__ char dsm[];
    const uint32_t sbase = smem_to_u32(dsm);
    const int tid = threadIdx.x;
    const int wid = tid >> 5, lane = tid & 31;
    const int warp_m = wid >> 2;
    const int warp_n = wid & 3;
    const int row0 = blockIdx.y * 128;
    const int col0 = blockIdx.x * 128;

    float acc[4][4][4];
#pragma unroll
    for (int i = 0; i < 4; i++)
#pragma unroll
        for (int j = 0; j < 4; j++)
#pragma unroll
            for (int q = 0; q < 4; q++) acc[i][j][q] = 0.f;

    GEMM_MAINLOOP(K >> 6)

    const int qr = lane >> 2;
    const int qc = (lane & 3) * 2;
#pragma unroll
    for (int mt = 0; mt < 4; mt++) {
#pragma unroll
        for (int nt = 0; nt < 4; nt++) {
            int col = col0 + warp_n * 32 + nt * 8 + qc;
            float b0 = bias[col], b1 = bias[col + 1];
            int r0 = row0 + warp_m * 64 + mt * 16 + qr;
            float2 v0 = { acc[mt][nt][0] + b0, acc[mt][nt][1] + b1 };
            float2 v1 = { acc[mt][nt][2] + b0, acc[mt][nt][3] + b1 };
            *(float2*)&C[(size_t)r0 * N + col] = v0;
            *(float2*)&C[(size_t)(r0 + 8) * N + col] = v1;
        }
    }
}

// ---------------- fused QKV GEMM: + RMSNorm + RoPE + fp16 outputs ------------
// grid (48, 32): blockIdx.x = type*16 + head.
__global__ __launch_bounds__(256, 2) void gemm_qkv_fused(
    const __half* __restrict__ A,
    const __half* __restrict__ Bh, const __half* __restrict__ Bl,
    const float* __restrict__ qw, const float* __restrict__ kw,
    const float* __restrict__ fcos, const float* __restrict__ fsin,
    int K)
{
    extern __shared__ char dsm[];
    const uint32_t sbase = smem_to_u32(dsm);
    const int tid = threadIdx.x;
    const int wid = tid >> 5, lane = tid & 31;
    const int warp_m = wid >> 2;
    const int warp_n = wid & 3;
    const int row0 = blockIdx.y * 128;
    const int col0 = blockIdx.x * 128;

    float acc[4][4][4];
#pragma unroll
    for (int i = 0; i < 4; i++)
#pragma unroll
        for (int j = 0; j < 4; j++)
#pragma unroll
            for (int q = 0; q < 4; q++) acc[i][j][q] = 0.f;

    GEMM_MAINLOOP(K >> 6)

    // ---- fused epilogue ----
    const int t  = blockIdx.x >> 4;     // 0=q, 1=k, 2=v
    const int hh = blockIdx.x & 15;
    const int qr = lane >> 2;
    const int qc = (lane & 3) * 2;

    __syncthreads();                    // MMA block done in all warps
    float* red = (float*)dsm;           // [128][4]

    float rstd[8];
#pragma unroll
    for (int j = 0; j < 8; j++) rstd[j] = 1.f;

    if (t < 2) {
#pragma unroll
        for (int mt = 0; mt < 4; mt++) {
#pragma unroll
            for (int half = 0; half < 2; half++) {
                float ss = 0.f;
#pragma unroll
                for (int nt = 0; nt < 4; nt++) {
                    float e = acc[mt][nt][half * 2], o_ = acc[mt][nt][half * 2 + 1];
                    ss += e * e + o_ * o_;
                }
                ss += __shfl_xor_sync(0xffffffffu, ss, 1);
                ss += __shfl_xor_sync(0xffffffffu, ss, 2);
                if ((lane & 3) == 0)
                    red[(warp_m * 64 + mt * 16 + half * 8 + qr) * 4 + warp_n] = ss;
            }
        }
        __syncthreads();
#pragma unroll
        for (int mt = 0; mt < 4; mt++)
#pragma unroll
            for (int half = 0; half < 2; half++) {
                int rl = warp_m * 64 + mt * 16 + half * 8 + qr;
                float tot = red[rl * 4] + red[rl * 4 + 1] + red[rl * 4 + 2] + red[rl * 4 + 3];
                rstd[mt * 2 + half] = rsqrtf(tot * (1.0f / Dn) + 1e-6f);
            }
    }

    const float* wnorm = (t == 0) ? qw : kw;
    const float tsc = (t == 0) ? 0.08838834764831845f : 1.0f;

#pragma unroll
    for (int mt = 0; mt < 4; mt++) {
#pragma unroll
        for (int half = 0; half < 2; half++) {
            int srow = row0 + warp_m * 64 + mt * 16 + half * 8 + qr;   // bs
            int b = srow >> 10, s = srow & 1023;
            size_t obase = ((size_t)(b * Hn + hh) * Sn + s) * Dn;
            float r = rstd[mt * 2 + half];
#pragma unroll
            for (int nt = 0; nt < 4; nt++) {
                int d0 = warp_n * 32 + nt * 8 + qc;
                float e  = acc[mt][nt][half * 2];
                float o_ = acc[mt][nt][half * 2 + 1];
                if (t == 0) {
                    e  = e  * r * wnorm[d0];
                    o_ = o_ * r * wnorm[d0 + 1];
                    float cs = fcos[(size_t)srow * (Dn / 2) + (d0 >> 1)];
                    float sn = fsin[(size_t)srow * (Dn / 2) + (d0 >> 1)];
                    float re = (e * cs - o_ * sn) * tsc;
                    float im = (e * sn + o_ * cs) * tsc;
                    *(uint32_t*)&g_q[obase + d0] = pack2h(re, im);
                } else if (t == 1) {
                    e  = e  * r * wnorm[d0];
                    o_ = o_ * r * wnorm[d0 + 1];
                    float cs = fcos[(size_t)srow * (Dn / 2) + (d0 >> 1)];
                    float sn = fsin[(size_t)srow * (Dn / 2) + (d0 >> 1)];
                    float re = e * cs - o_ * sn;
                    float im = e * sn + o_ * cs;
                    uint32_t hiw, low;
                    split2h(re, im, hiw, low);
                    *(uint32_t*)&g_kh[obase + d0] = hiw;
                    *(uint32_t*)&g_kl[obase + d0] = low;
                } else {
                    uint32_t hiw, low;
                    split2h(e, o_, hiw, low);
                    *(uint32_t*)&g_vh[obase + d0] = hiw;
                    *(uint32_t*)&g_vl[obase + d0] = low;
                }
            }
        }
    }
}

// ---------------- fp32 -> fp16 convert, elementwise --------------------------
__global__ __launch_bounds__(256) void cvt_kernel(
    const float* __restrict__ in, __half* __restrict__ out, int n)
{
    int i = blockIdx.x * blockDim.x + threadIdx.x;
    if (i < n) out[i] = __float2half_rn(in[i]);
}

// ---------------- transpose + split: W[K,N] -> T[N,K] hi/lo fp16 -------------
__global__ __launch_bounds__(256) void transpose_split_kernel(
    const float* __restrict__ W, __half* __restrict__ Th,
    __half* __restrict__ Tl, int K, int N)
{
    __shared__ float t[32][33];
    int tx = threadIdx.x, ty = threadIdx.y;
    int n0 = blockIdx.x * 32, k0 = blockIdx.y * 32;
#pragma unroll
    for (int i = ty; i < 32; i += 8)
        t[i][tx] = W[(size_t)(k0 + i) * N + n0 + tx];
    __syncthreads();
#pragma unroll
    for (int i = ty; i < 32; i += 8) {
        float v = t[tx][i];
        __half h = __float2half_rn(v);
        float r = v - __half2float(h);
        size_t o = (size_t)(n0 + i) * K + k0 + tx;
        Th[o] = h;
        Tl[o] = __float2half_rn(r);
    }
}

// ---------------- flash attention, fp16 2-term -------------------------------
#define ARS   136                    // smem row stride (fp16 elems) = 272 B
#define ATILE (64 * ARS * 2)         // 17408
#define AQT   (128 * ARS * 2)        // 34816

__global__ __launch_bounds__(256) void attn_mma()
{
    extern __shared__ char asmem[];
    const uint32_t sb = smem_to_u32(asmem);
    const uint32_t sQ = sb;
    const uint32_t sStage = sb + AQT;   // + stage*4*ATILE: kh,kl,vh,vl

    const int tid = threadIdx.x;
    const int wid = tid >> 5, lane = tid & 31;
    const int bh = blockIdx.y;
    const int q0 = blockIdx.x * 128;
    const int b = bh / Hn, h = bh % Hn;

    const __half* qg = g_q  + (size_t)bh * Sn * Dn;
    const __half* kh = g_kh + (size_t)bh * Sn * Dn;
    const __half* kl = g_kl + (size_t)bh * Sn * Dn;
    const __half* vh = g_vh + (size_t)bh * Sn * Dn;
    const __half* vl = g_vl + (size_t)bh * Sn * Dn;

    // q tile: 128 rows x 16 chunks = 2048 cp16
#pragma unroll
    for (int it = 0; it < 8; it++) {
        int idx = tid + it * 256;
        int r = idx >> 4, ch = idx & 15;
        cp16(sQ + (uint32_t)r * (ARS * 2) + (uint32_t)ch * 16,
             qg + (size_t)(q0 + r) * Dn + ch * 8);
    }

    auto fill = [&](int stage, int c) {
        uint32_t base = sStage + (uint32_t)stage * 4 * ATILE;
        int k0 = c * 64;
#pragma unroll
        for (int it = 0; it < 16; it++) {
            int idx = tid + it * 256;
            int arr = idx >> 10;
            int rem = idx & 1023;
            int r = rem >> 4, ch = rem & 15;
            const __half* s =
                (arr == 0 ? kh : arr == 1 ? kl : arr == 2 ? vh : vl)
                + (size_t)(k0 + r) * Dn + ch * 8;
            cp16(base + (uint32_t)arr * ATILE + (uint32_t)r * (ARS * 2) + (uint32_t)ch * 16, s);
        }
        cp_commit();
    };

    fill(0, 0);   // group also contains q loads

    float o[16][4];
#pragma unroll
    for (int i = 0; i < 16; i++)
#pragma unroll
        for (int j = 0; j < 4; j++) o[i][j] = 0.f;
    float m0 = -CUDART_INF_F, m1 = -CUDART_INF_F, l0 = 0.f, l1 = 0.f;

    const int arow = wid * 16 + (lane & 15);
    const uint32_t aoff_base = (uint32_t)arow * (ARS * 2) + (uint32_t)((lane >> 4) * 8) * 2;
    const int brow = (lane & 7) + ((lane >> 4) << 3);
    const int vkey = (lane & 7) + (((lane >> 3) & 1) << 3);
    const uint32_t vcolb = (uint32_t)((lane >> 4) << 3) * 2;

    for (int c = 0; c < 16; c++) {
        if (c + 1 < 16) fill((c + 1) & 1, c + 1);
        if (c + 1 < 16) cp_wait1(); else cp_wait0();
        __syncthreads();

        uint32_t st = sStage + (uint32_t)(c & 1) * 4 * ATILE;
        uint32_t sKh = st, sKl = st + ATILE, sVh = st + 2 * ATILE, sVl = st + 3 * ATILE;

        float s[8][4];
#pragma unroll
        for (int i = 0; i < 8; i++)
#pragma unroll
            for (int j = 0; j < 4; j++) s[i][j] = 0.f;

#pragma unroll
        for (int ks = 0; ks < 8; ks++) {
            const int kc = ks * 16;
            uint32_t ah[4];
            ldm_x4(ah, sQ + aoff_base + (uint32_t)kc * 2);
            const uint32_t bcol = (uint32_t)(kc + ((lane >> 3) & 1) * 8) * 2;
#pragma unroll
            for (int np = 0; np < 4; np++) {
                uint32_t bh4[4], bl4[4];
                uint32_t boff = (uint32_t)(np * 16 + brow) * (ARS * 2) + bcol;
                ldm_x4(bh4, sKh + boff);
                ldm_x4(bl4, sKl + boff);
                mma_f16(s[2 * np],     ah, &bh4[0]);
                mma_f16(s[2 * np],     ah, &bl4[0]);
                mma_f16(s[2 * np + 1], ah, &bh4[2]);
                mma_f16(s[2 * np + 1], ah, &bl4[2]);
            }
        }

        float tmax0 = -CUDART_INF_F, tmax1 = -CUDART_INF_F;
#pragma unroll
        for (int nt = 0; nt < 8; nt++) {
            tmax0 = fmaxf(tmax0, fmaxf(s[nt][0], s[nt][1]));
            tmax1 = fmaxf(tmax1, fmaxf(s[nt][2], s[nt][3]));
        }
        tmax0 = fmaxf(tmax0, __shfl_xor_sync(0xffffffffu, tmax0, 1));
        tmax0 = fmaxf(tmax0, __shfl_xor_sync(0xffffffffu, tmax0, 2));
        tmax1 = fmaxf(tmax1, __shfl_xor_sync(0xffffffffu, tmax1, 1));
        tmax1 = fmaxf(tmax1, __shfl_xor_sync(0xffffffffu, tmax1, 2));
        float mn0 = fmaxf(m0, tmax0), mn1 = fmaxf(m1, tmax1);
        float al0 = __expf(m0 - mn0), al1 = __expf(m1 - mn1);
        m0 = mn0; m1 = mn1;
        float ps0 = 0.f, ps1 = 0.f;
#pragma unroll
        for (int nt = 0; nt < 8; nt++) {
            s[nt][0] = __expf(s[nt][0] - mn0);
            s[nt][1] = __expf(s[nt][1] - mn0);
            s[nt][2] = __expf(s[nt][2] - mn1);
            s[nt][3] = __expf(s[nt][3] - mn1);
            ps0 += s[nt][0] + s[nt][1];
            ps1 += s[nt][2] + s[nt][3];
        }
        l0 = l0 * al0 + ps0;
        l1 = l1 * al1 + ps1;
#pragma unroll
        for (int i = 0; i < 16; i++) {
            o[i][0] *= al0; o[i][1] *= al0;
            o[i][2] *= al1; o[i][3] *= al1;
        }

#pragma unroll
        for (int k2 = 0; k2 < 4; k2++) {
            uint32_t aP[4];
            aP[0] = pack2h(s[2 * k2][0],     s[2 * k2][1]);
            aP[1] = pack2h(s[2 * k2][2],     s[2 * k2][3]);
            aP[2] = pack2h(s[2 * k2 + 1][0], s[2 * k2 + 1][1]);
            aP[3] = pack2h(s[2 * k2 + 1][2], s[2 * k2 + 1][3]);
            const uint32_t vrow = (uint32_t)(k2 * 16 + vkey) * (ARS * 2);
#pragma unroll
            for (int np = 0; np < 8; np++) {
                uint32_t bvh[4], bvl[4];
                uint32_t voff = vrow + (uint32_t)(np * 16) * 2 + vcolb;
                ldm_x4_t(bvh, sVh + voff);
                ldm_x4_t(bvl, sVl + voff);
                mma_f16(o[2 * np],     aP, &bvh[0]);
                mma_f16(o[2 * np],     aP, &bvl[0]);
                mma_f16(o[2 * np + 1], aP, &bvh[2]);
                mma_f16(o[2 * np + 1], aP, &bvl[2]);
            }
        }
        __syncthreads();
    }

    l0 += __shfl_xor_sync(0xffffffffu, l0, 1);
    l0 += __shfl_xor_sync(0xffffffffu, l0, 2);
    l1 += __shfl_xor_sync(0xffffffffu, l1, 1);
    l1 += __shfl_xor_sync(0xffffffffu, l1, 2);
    float inv0 = 1.f / l0, inv1 = 1.f / l1;

    const int row0 = q0 + wid * 16 + (lane >> 2);
    const int colb = (lane & 3) * 2;
#pragma unroll
    for (int nt = 0; nt < 16; nt++) {
        int col = nt * 8 + colb;
        size_t i0 = (size_t)(b * Sn + row0) * Cn + h * Dn + col;
        size_t i1 = (size_t)(b * Sn + row0 + 8) * Cn + h * Dn + col;
        *(uint32_t*)&g_o[i0] = pack2h(o[nt][0] * inv0, o[nt][1] * inv0);
        *(uint32_t*)&g_o[i1] = pack2h(o[nt][2] * inv1, o[nt][3] * inv1);
    }
}

// ---------------- launch ----------------------------------------------------
extern "C" void kernel_launch(void* const* d_in, const int* in_sizes, int n_in,
                              void* d_out, int out_size)
{
    const float* x      = (const float*)d_in[0];
    const float* W_qkv  = (const float*)d_in[1];
    const float* q_w    = (const float*)d_in[2];
    const float* k_w    = (const float*)d_in[3];
    const float* W_proj = (const float*)d_in[4];
    const float* b_proj = (const float*)d_in[5];
    const float* fcos   = (const float*)d_in[6];
    const float* fsin   = (const float*)d_in[7];
    float* out = (float*)d_out;

    __half *p_x, *p_o, *p_wqh, *p_wql, *p_wph, *p_wpl;
    cudaGetSymbolAddress((void**)&p_x,   g_x);
    cudaGetSymbolAddress((void**)&p_o,   g_o);
    cudaGetSymbolAddress((void**)&p_wqh, g_wqkvT_h);
    cudaGetSymbolAddress((void**)&p_wql, g_wqkvT_l);
    cudaGetSymbolAddress((void**)&p_wph, g_wprojT_h);
    cudaGetSymbolAddress((void**)&p_wpl, g_wprojT_l);

    constexpr int GEMM_SMEM = 2 * STAGE_BYTES;            // 110592 B
    constexpr int ATTN_SMEM = AQT + 2 * 4 * ATILE;        // 174080 B
    static bool attr_set = false;
    if (!attr_set) {
        cudaFuncSetAttribute(gemm_mma, cudaFuncAttributeMaxDynamicSharedMemorySize, GEMM_SMEM);
        cudaFuncSetAttribute(gemm_qkv_fused, cudaFuncAttributeMaxDynamicSharedMemorySize, GEMM_SMEM);
        cudaFuncSetAttribute(attn_mma, cudaFuncAttributeMaxDynamicSharedMemorySize, ATTN_SMEM);
        attr_set = true;
    }

    // 0) operand conversions
    {
        int n = BSn * Cn;
        cvt_kernel<<<(n + 255) / 256, 256>>>(x, p_x, n);
        dim3 blk(32, 8);
        transpose_split_kernel<<<dim3(NQKV / 32, Cn / 32), blk>>>(W_qkv, p_wqh, p_wql, Cn, NQKV);
        transpose_split_kernel<<<dim3(Cn / 32, Cn / 32), blk>>>(W_proj, p_wph, p_wpl, Cn, Cn);
    }
    // 1) qkv = x @ W_qkv, fused with rmsnorm + rope
    {
        dim3 grid(NQKV / 128, BSn / 128);
        gemm_qkv_fused<<<grid, 256, GEMM_SMEM>>>(p_x, p_wqh, p_wql,
                                                 q_w, k_w, fcos, fsin, Cn);
    }
    // 2) attention (mma.sync fp16)
    {
        dim3 grid(Sn / 128, Bn * Hn);
        attn_mma<<<grid, 256, ATTN_SMEM>>>();
    }
    // 3) out = o @ W_proj + b_proj
    {
        dim3 grid(Cn / 128, BSn / 128);
        gemm_mma<<<grid, 256, GEMM_SMEM>>>(p_o, p_wph, p_wpl, b_proj, out,
                                           BSn, Cn, Cn);
    }
}

// round 17
// speedup vs baseline: 1.3814x; 1.0281x over previous
#include <cuda_runtime.h>
#include <cuda_fp16.h>
#include <math_constants.h>
#include <cstdint>

#define Bn  4
#define Sn  1024
#define Cn  2048
#define Hn  16
#define Dn  128
#define BSn (Bn*Sn)       // 4096
#define NQKV (3*Cn)       // 6144

// ---------------- scratch (device globals; no allocations allowed) ----------
__device__ __half g_q [(size_t)Bn*Hn*Sn*Dn];          // q hi (pre-scaled 1/sqrt(D))
__device__ __half g_kh[(size_t)Bn*Hn*Sn*Dn];
__device__ __half g_kl[(size_t)Bn*Hn*Sn*Dn];
__device__ __half g_vh[(size_t)Bn*Hn*Sn*Dn];

__device__ __half g_x [(size_t)BSn*Cn];               // x hi
__device__ __half g_o [(size_t)BSn*Cn];               // attention out hi
__device__ __half g_wqkvT_h[(size_t)NQKV*Cn];         // [N,K]
__device__ __half g_wqkvT_l[(size_t)NQKV*Cn];
__device__ __half g_wprojT_h[(size_t)Cn*Cn];
__device__ __half g_wprojT_l[(size_t)Cn*Cn];

// =================== helpers ================================================
__device__ __forceinline__ uint32_t smem_to_u32(const void* p) {
    uint32_t a;
    asm("{ .reg .u64 t; cvta.to.shared.u64 t, %1; cvt.u32.u64 %0, t; }"
        : "=r"(a) : "l"(p));
    return a;
}
__device__ __forceinline__ void cp16(uint32_t dst, const void* src) {
    asm volatile("cp.async.cg.shared.global [%0], [%1], 16;" :: "r"(dst), "l"(src));
}
__device__ __forceinline__ void cp_commit() { asm volatile("cp.async.commit_group;"); }
__device__ __forceinline__ void cp_wait1()  { asm volatile("cp.async.wait_group 1;" ::: "memory"); }
__device__ __forceinline__ void cp_wait0()  { asm volatile("cp.async.wait_group 0;" ::: "memory"); }

__device__ __forceinline__ void ldm_x4(uint32_t* r, uint32_t addr) {
    asm volatile("ldmatrix.sync.aligned.m8n8.x4.shared.b16 {%0,%1,%2,%3}, [%4];"
        : "=r"(r[0]), "=r"(r[1]), "=r"(r[2]), "=r"(r[3]) : "r"(addr));
}
__device__ __forceinline__ void ldm_x4_t(uint32_t* r, uint32_t addr) {
    asm volatile("ldmatrix.sync.aligned.m8n8.x4.trans.shared.b16 {%0,%1,%2,%3}, [%4];"
        : "=r"(r[0]), "=r"(r[1]), "=r"(r[2]), "=r"(r[3]) : "r"(addr));
}
__device__ __forceinline__ void mma_f16(float* d, const uint32_t* a, const uint32_t* b) {
    asm volatile(
        "mma.sync.aligned.m16n8k16.row.col.f32.f16.f16.f32 "
        "{%0,%1,%2,%3}, {%4,%5,%6,%7}, {%8,%9}, {%0,%1,%2,%3};"
        : "+f"(d[0]), "+f"(d[1]), "+f"(d[2]), "+f"(d[3])
        : "r"(a[0]), "r"(a[1]), "r"(a[2]), "r"(a[3]), "r"(b[0]), "r"(b[1]));
}
__device__ __forceinline__ uint32_t pack2h(float e0, float e1) {
    __half2 t = __floats2half2_rn(e0, e1);
    return *(uint32_t*)&t;
}
__device__ __forceinline__ void split2h(float e0, float e1, uint32_t& hi, uint32_t& lo) {
    __half h0 = __float2half_rn(e0), h1 = __float2half_rn(e1);
    __half2 hp = __halves2half2(h0, h1);
    hi = *(uint32_t*)&hp;
    lo = pack2h(e0 - __half2float(h0), e1 - __half2float(h1));
}

// ---------------- shared GEMM mainloop (fp16 2-term, BK=64) ------------------
#define RSB 144                          // row stride bytes (64 fp16 + 8 pad)
#define ARRB (128 * RSB)                 // one array block: 18432 B
#define STAGE_BYTES (3 * ARRB)           // A, Bh, Bl = 55296 B

#define GEMM_FILL(stage, k0)                                                     \
    do {                                                                         \
        uint32_t sbf = sbase + (uint32_t)(stage) * STAGE_BYTES;                  \
        cp16(sbf + fso,                  A  + offA + (k0));                      \
        cp16(sbf + fso + 64,             A  + offA + (k0) + 32);                 \
        cp16(sbf + fso2,                 A  + offA64 + (k0));                    \
        cp16(sbf + fso2 + 64,            A  + offA64 + (k0) + 32);               \
        cp16(sbf + ARRB + fso,           Bh + offB + (k0));                      \
        cp16(sbf + ARRB + fso + 64,      Bh + offB + (k0) + 32);                 \
        cp16(sbf + ARRB + fso2,          Bh + offB64 + (k0));                    \
        cp16(sbf + ARRB + fso2 + 64,     Bh + offB64 + (k0) + 32);               \
        cp16(sbf + 2 * ARRB + fso,       Bl + offB + (k0));                      \
        cp16(sbf + 2 * ARRB + fso + 64,  Bl + offB + (k0) + 32);                 \
        cp16(sbf + 2 * ARRB + fso2,      Bl + offB64 + (k0));                    \
        cp16(sbf + 2 * ARRB + fso2 + 64, Bl + offB64 + (k0) + 32);               \
        cp_commit();                                                             \
    } while (0)

#define GEMM_LDSM(ks, AH, BH, BL)                                                \
    do {                                                                         \
        const int kc = (ks) * 16;                                                \
        _Pragma("unroll")                                                        \
        for (int mt = 0; mt < 4; mt++) {                                         \
            uint32_t roff = (uint32_t)(warp_m * 64 + mt * 16 + lm) * RSB         \
                          + (uint32_t)(kc + lk8 * 8) * 2;                        \
            ldm_x4(AH[mt], sA + roff);                                           \
        }                                                                        \
        _Pragma("unroll")                                                        \
        for (int ntp = 0; ntp < 2; ntp++) {                                      \
            uint32_t roff = (uint32_t)(warp_n * 32 + ntp * 16 + brw) * RSB       \
                          + (uint32_t)(kc + bkh * 8) * 2;                        \
            ldm_x4(BH[ntp], sBh + roff);                                         \
            ldm_x4(BL[ntp], sBl + roff);                                         \
        }                                                                        \
    } while (0)

#define GEMM_MMAS(AH, BH, BL)                                                    \
    do {                                                                         \
        _Pragma("unroll")                                                        \
        for (int ntp = 0; ntp < 2; ntp++)                                        \
            _Pragma("unroll")                                                    \
            for (int mt = 0; mt < 4; mt++) {                                     \
                mma_f16(acc[mt][2 * ntp],     AH[mt], &BH[ntp][0]);              \
                mma_f16(acc[mt][2 * ntp],     AH[mt], &BL[ntp][0]);              \
                mma_f16(acc[mt][2 * ntp + 1], AH[mt], &BH[ntp][2]);              \
                mma_f16(acc[mt][2 * ntp + 1], AH[mt], &BL[ntp][2]);              \
            }                                                                    \
    } while (0)

#define GEMM_MAINLOOP(NCexpr)                                                    \
    const int NC = (NCexpr);                                                     \
    const int lm   = lane & 15;                                                  \
    const int lk8  = lane >> 4;                                                  \
    const int brw  = (lane & 7) + ((lane >> 4) << 3);                            \
    const int bkh  = (lane >> 3) & 1;                                            \
    const int fr   = tid >> 2;                                                   \
    const int fch  = tid & 3;                                                    \
    const size_t offA   = (size_t)(row0 + fr) * K + fch * 8;                     \
    const size_t offA64 = offA + (size_t)64 * K;                                 \
    const size_t offB   = (size_t)(col0 + fr) * K + fch * 8;                     \
    const size_t offB64 = offB + (size_t)64 * K;                                 \
    const uint32_t fso  = (uint32_t)fr * RSB + (uint32_t)fch * 16;               \
    const uint32_t fso2 = fso + 64u * RSB;                                       \
    GEMM_FILL(0, 0);                                                             \
    for (int c = 0; c < NC; c++) {                                               \
        if (c + 1 < NC) GEMM_FILL((c + 1) & 1, (c + 1) << 6);                    \
        if (c + 1 < NC) cp_wait1(); else cp_wait0();                             \
        __syncthreads();                                                         \
        uint32_t sbf = sbase + (uint32_t)(c & 1) * STAGE_BYTES;                  \
        uint32_t sA  = sbf;                                                      \
        uint32_t sBh = sbf + ARRB;                                               \
        uint32_t sBl = sbf + 2 * ARRB;                                           \
        _Pragma("unroll")                                                        \
        for (int ks = 0; ks < 4; ks++) {                                         \
            uint32_t ah[4][4], bh[2][4], bl[2][4];                               \
            GEMM_LDSM(ks, ah, bh, bl);                                           \
            if (ks == 3) __syncthreads();                                        \
            GEMM_MMAS(ah, bh, bl);                                               \
        }                                                                        \
    }

// ---------------- plain GEMM (proj): fp32 out + bias -------------------------
__global__ __launch_bounds__(256, 2) void gemm_mma(
    const __half* __restrict__ A,
    const __half* __restrict__ Bh, const __half* __restrict__ Bl,
    const float* __restrict__ bias, float* __restrict__ C,
    int M, int N, int K)
{
    extern __shared__ char dsm[];
    const uint32_t sbase = smem_to_u32(dsm);
    const int tid = threadIdx.x;
    const int wid = tid >> 5, lane = tid & 31;
    const int warp_m = wid >> 2;
    const int warp_n = wid & 3;
    const int row0 = blockIdx.y * 128;
    const int col0 = blockIdx.x * 128;

    float acc[4][4][4];
#pragma unroll
    for (int i = 0; i < 4; i++)
#pragma unroll
        for (int j = 0; j < 4; j++)
#pragma unroll
            for (int q = 0; q < 4; q++) acc[i][j][q] = 0.f;

    GEMM_MAINLOOP(K >> 6)

    const int qr = lane >> 2;
    const int qc = (lane & 3) * 2;
#pragma unroll
    for (int mt = 0; mt < 4; mt++) {
#pragma unroll
        for (int nt = 0; nt < 4; nt++) {
            int col = col0 + warp_n * 32 + nt * 8 + qc;
            float b0 = bias[col], b1 = bias[col + 1];
            int r0 = row0 + warp_m * 64 + mt * 16 + qr;
            float2 v0 = { acc[mt][nt][0] + b0, acc[mt][nt][1] + b1 };
            float2 v1 = { acc[mt][nt][2] + b0, acc[mt][nt][3] + b1 };
            *(float2*)&C[(size_t)r0 * N + col] = v0;
            *(float2*)&C[(size_t)(r0 + 8) * N + col] = v1;
        }
    }
}

// ---------------- fused QKV GEMM: + RMSNorm + RoPE + fp16 outputs ------------
// grid (48, 32): blockIdx.x = type*16 + head.
__global__ __launch_bounds__(256, 2) void gemm_qkv_fused(
    const __half* __restrict__ A,
    const __half* __restrict__ Bh, const __half* __restrict__ Bl,
    const float* __restrict__ qw, const float* __restrict__ kw,
    const float* __restrict__ fcos, const float* __restrict__ fsin,
    int K)
{
    extern __shared__ char dsm[];
    const uint32_t sbase = smem_to_u32(dsm);
    const int tid = threadIdx.x;
    const int wid = tid >> 5, lane = tid & 31;
    const int warp_m = wid >> 2;
    const int warp_n = wid & 3;
    const int row0 = blockIdx.y * 128;
    const int col0 = blockIdx.x * 128;

    float acc[4][4][4];
#pragma unroll
    for (int i = 0; i < 4; i++)
#pragma unroll
        for (int j = 0; j < 4; j++)
#pragma unroll
            for (int q = 0; q < 4; q++) acc[i][j][q] = 0.f;

    GEMM_MAINLOOP(K >> 6)

    // ---- fused epilogue ----
    const int t  = blockIdx.x >> 4;     // 0=q, 1=k, 2=v
    const int hh = blockIdx.x & 15;
    const int qr = lane >> 2;
    const int qc = (lane & 3) * 2;

    __syncthreads();                    // MMA block done in all warps
    float* red = (float*)dsm;           // [128][4]

    float rstd[8];
#pragma unroll
    for (int j = 0; j < 8; j++) rstd[j] = 1.f;

    if (t < 2) {
#pragma unroll
        for (int mt = 0; mt < 4; mt++) {
#pragma unroll
            for (int half = 0; half < 2; half++) {
                float ss = 0.f;
#pragma unroll
                for (int nt = 0; nt < 4; nt++) {
                    float e = acc[mt][nt][half * 2], o_ = acc[mt][nt][half * 2 + 1];
                    ss += e * e + o_ * o_;
                }
                ss += __shfl_xor_sync(0xffffffffu, ss, 1);
                ss += __shfl_xor_sync(0xffffffffu, ss, 2);
                if ((lane & 3) == 0)
                    red[(warp_m * 64 + mt * 16 + half * 8 + qr) * 4 + warp_n] = ss;
            }
        }
        __syncthreads();
#pragma unroll
        for (int mt = 0; mt < 4; mt++)
#pragma unroll
            for (int half = 0; half < 2; half++) {
                int rl = warp_m * 64 + mt * 16 + half * 8 + qr;
                float tot = red[rl * 4] + red[rl * 4 + 1] + red[rl * 4 + 2] + red[rl * 4 + 3];
                rstd[mt * 2 + half] = rsqrtf(tot * (1.0f / Dn) + 1e-6f);
            }
    }

    const float* wnorm = (t == 0) ? qw : kw;
    const float tsc = (t == 0) ? 0.08838834764831845f : 1.0f;

#pragma unroll
    for (int mt = 0; mt < 4; mt++) {
#pragma unroll
        for (int half = 0; half < 2; half++) {
            int srow = row0 + warp_m * 64 + mt * 16 + half * 8 + qr;   // bs
            int b = srow >> 10, s = srow & 1023;
            size_t obase = ((size_t)(b * Hn + hh) * Sn + s) * Dn;
            float r = rstd[mt * 2 + half];
#pragma unroll
            for (int nt = 0; nt < 4; nt++) {
                int d0 = warp_n * 32 + nt * 8 + qc;
                float e  = acc[mt][nt][half * 2];
                float o_ = acc[mt][nt][half * 2 + 1];
                if (t == 0) {
                    e  = e  * r * wnorm[d0];
                    o_ = o_ * r * wnorm[d0 + 1];
                    float cs = fcos[(size_t)srow * (Dn / 2) + (d0 >> 1)];
                    float sn = fsin[(size_t)srow * (Dn / 2) + (d0 >> 1)];
                    float re = (e * cs - o_ * sn) * tsc;
                    float im = (e * sn + o_ * cs) * tsc;
                    *(uint32_t*)&g_q[obase + d0] = pack2h(re, im);
                } else if (t == 1) {
                    e  = e  * r * wnorm[d0];
                    o_ = o_ * r * wnorm[d0 + 1];
                    float cs = fcos[(size_t)srow * (Dn / 2) + (d0 >> 1)];
                    float sn = fsin[(size_t)srow * (Dn / 2) + (d0 >> 1)];
                    float re = e * cs - o_ * sn;
                    float im = e * sn + o_ * cs;
                    uint32_t hiw, low;
                    split2h(re, im, hiw, low);
                    *(uint32_t*)&g_kh[obase + d0] = hiw;
                    *(uint32_t*)&g_kl[obase + d0] = low;
                } else {
                    *(uint32_t*)&g_vh[obase + d0] = pack2h(e, o_);
                }
            }
        }
    }
}

// ---------------- fp32 -> fp16 convert, elementwise --------------------------
__global__ __launch_bounds__(256) void cvt_kernel(
    const float* __restrict__ in, __half* __restrict__ out, int n)
{
    int i = blockIdx.x * blockDim.x + threadIdx.x;
    if (i < n) out[i] = __float2half_rn(in[i]);
}

// ---------------- transpose + split: W[K,N] -> T[N,K] hi/lo fp16 -------------
__global__ __launch_bounds__(256) void transpose_split_kernel(
    const float* __restrict__ W, __half* __restrict__ Th,
    __half* __restrict__ Tl, int K, int N)
{
    __shared__ float t[32][33];
    int tx = threadIdx.x, ty = threadIdx.y;
    int n0 = blockIdx.x * 32, k0 = blockIdx.y * 32;
#pragma unroll
    for (int i = ty; i < 32; i += 8)
        t[i][tx] = W[(size_t)(k0 + i) * N + n0 + tx];
    __syncthreads();
#pragma unroll
    for (int i = ty; i < 32; i += 8) {
        float v = t[tx][i];
        __half h = __float2half_rn(v);
        float r = v - __half2float(h);
        size_t o = (size_t)(n0 + i) * K + k0 + tx;
        Th[o] = h;
        Tl[o] = __float2half_rn(r);
    }
}

// ---------------- flash attention, fp16 (K 2-term, PV 1-term) ----------------
#define ARS   136                    // smem row stride (fp16 elems) = 272 B
#define ATILE (64 * ARS * 2)         // 17408
#define AQT   (128 * ARS * 2)        // 34816

__global__ __launch_bounds__(256) void attn_mma()
{
    extern __shared__ char asmem[];
    const uint32_t sb = smem_to_u32(asmem);
    const uint32_t sQ = sb;
    const uint32_t sStage = sb + AQT;   // + stage*3*ATILE: kh,kl,vh

    const int tid = threadIdx.x;
    const int wid = tid >> 5, lane = tid & 31;
    const int bh = blockIdx.y;
    const int q0 = blockIdx.x * 128;
    const int b = bh / Hn, h = bh % Hn;

    const __half* qg = g_q  + (size_t)bh * Sn * Dn;
    const __half* kh = g_kh + (size_t)bh * Sn * Dn;
    const __half* kl = g_kl + (size_t)bh * Sn * Dn;
    const __half* vh = g_vh + (size_t)bh * Sn * Dn;

    // q tile: 128 rows x 16 chunks = 2048 cp16
#pragma unroll
    for (int it = 0; it < 8; it++) {
        int idx = tid + it * 256;
        int r = idx >> 4, ch = idx & 15;
        cp16(sQ + (uint32_t)r * (ARS * 2) + (uint32_t)ch * 16,
             qg + (size_t)(q0 + r) * Dn + ch * 8);
    }

    auto fill = [&](int stage, int c) {
        uint32_t base = sStage + (uint32_t)stage * 3 * ATILE;
        int k0 = c * 64;
        // 3 arrays x 64 rows x 16 chunks = 3072 cp16 = 12 per thread
#pragma unroll
        for (int it = 0; it < 12; it++) {
            int idx = tid + it * 256;
            int arr = idx >> 10;
            int rem = idx & 1023;
            int r = rem >> 4, ch = rem & 15;
            const __half* s =
                (arr == 0 ? kh : arr == 1 ? kl : vh)
                + (size_t)(k0 + r) * Dn + ch * 8;
            cp16(base + (uint32_t)arr * ATILE + (uint32_t)r * (ARS * 2) + (uint32_t)ch * 16, s);
        }
        cp_commit();
    };

    fill(0, 0);   // group also contains q loads

    float o[16][4];
#pragma unroll
    for (int i = 0; i < 16; i++)
#pragma unroll
        for (int j = 0; j < 4; j++) o[i][j] = 0.f;
    float m0 = -CUDART_INF_F, m1 = -CUDART_INF_F, l0 = 0.f, l1 = 0.f;

    const int arow = wid * 16 + (lane & 15);
    const uint32_t aoff_base = (uint32_t)arow * (ARS * 2) + (uint32_t)((lane >> 4) * 8) * 2;
    const int brow = (lane & 7) + ((lane >> 4) << 3);
    const int vkey = (lane & 7) + (((lane >> 3) & 1) << 3);
    const uint32_t vcolb = (uint32_t)((lane >> 4) << 3) * 2;

    for (int c = 0; c < 16; c++) {
        if (c + 1 < 16) fill((c + 1) & 1, c + 1);
        if (c + 1 < 16) cp_wait1(); else cp_wait0();
        __syncthreads();

        uint32_t st = sStage + (uint32_t)(c & 1) * 3 * ATILE;
        uint32_t sKh = st, sKl = st + ATILE, sVh = st + 2 * ATILE;

        float s[8][4];
#pragma unroll
        for (int i = 0; i < 8; i++)
#pragma unroll
            for (int j = 0; j < 4; j++) s[i][j] = 0.f;

#pragma unroll
        for (int ks = 0; ks < 8; ks++) {
            const int kc = ks * 16;
            uint32_t ah[4];
            ldm_x4(ah, sQ + aoff_base + (uint32_t)kc * 2);
            const uint32_t bcol = (uint32_t)(kc + ((lane >> 3) & 1) * 8) * 2;
#pragma unroll
            for (int np = 0; np < 4; np++) {
                uint32_t bh4[4], bl4[4];
                uint32_t boff = (uint32_t)(np * 16 + brow) * (ARS * 2) + bcol;
                ldm_x4(bh4, sKh + boff);
                ldm_x4(bl4, sKl + boff);
                mma_f16(s[2 * np],     ah, &bh4[0]);
                mma_f16(s[2 * np],     ah, &bl4[0]);
                mma_f16(s[2 * np + 1], ah, &bh4[2]);
                mma_f16(s[2 * np + 1], ah, &bl4[2]);
            }
        }

        float tmax0 = -CUDART_INF_F, tmax1 = -CUDART_INF_F;
#pragma unroll
        for (int nt = 0; nt < 8; nt++) {
            tmax0 = fmaxf(tmax0, fmaxf(s[nt][0], s[nt][1]));
            tmax1 = fmaxf(tmax1, fmaxf(s[nt][2], s[nt][3]));
        }
        tmax0 = fmaxf(tmax0, __shfl_xor_sync(0xffffffffu, tmax0, 1));
        tmax0 = fmaxf(tmax0, __shfl_xor_sync(0xffffffffu, tmax0, 2));
        tmax1 = fmaxf(tmax1, __shfl_xor_sync(0xffffffffu, tmax1, 1));
        tmax1 = fmaxf(tmax1, __shfl_xor_sync(0xffffffffu, tmax1, 2));
        float mn0 = fmaxf(m0, tmax0), mn1 = fmaxf(m1, tmax1);
        float al0 = __expf(m0 - mn0), al1 = __expf(m1 - mn1);
        m0 = mn0; m1 = mn1;
        float ps0 = 0.f, ps1 = 0.f;
#pragma unroll
        for (int nt = 0; nt < 8; nt++) {
            s[nt][0] = __expf(s[nt][0] - mn0);
            s[nt][1] = __expf(s[nt][1] - mn0);
            s[nt][2] = __expf(s[nt][2] - mn1);
            s[nt][3] = __expf(s[nt][3] - mn1);
            ps0 += s[nt][0] + s[nt][1];
            ps1 += s[nt][2] + s[nt][3];
        }
        l0 = l0 * al0 + ps0;
        l1 = l1 * al1 + ps1;
#pragma unroll
        for (int i = 0; i < 16; i++) {
            o[i][0] *= al0; o[i][1] *= al0;
            o[i][2] *= al1; o[i][3] *= al1;
        }

#pragma unroll
        for (int k2 = 0; k2 < 4; k2++) {
            uint32_t aP[4];
            aP[0] = pack2h(s[2 * k2][0],     s[2 * k2][1]);
            aP[1] = pack2h(s[2 * k2][2],     s[2 * k2][3]);
            aP[2] = pack2h(s[2 * k2 + 1][0], s[2 * k2 + 1][1]);
            aP[3] = pack2h(s[2 * k2 + 1][2], s[2 * k2 + 1][3]);
            const uint32_t vrow = (uint32_t)(k2 * 16 + vkey) * (ARS * 2);
#pragma unroll
            for (int np = 0; np < 8; np++) {
                uint32_t bvh[4];
                uint32_t voff = vrow + (uint32_t)(np * 16) * 2 + vcolb;
                ldm_x4_t(bvh, sVh + voff);
                mma_f16(o[2 * np],     aP, &bvh[0]);
                mma_f16(o[2 * np + 1], aP, &bvh[2]);
            }
        }
        __syncthreads();
    }

    l0 += __shfl_xor_sync(0xffffffffu, l0, 1);
    l0 += __shfl_xor_sync(0xffffffffu, l0, 2);
    l1 += __shfl_xor_sync(0xffffffffu, l1, 1);
    l1 += __shfl_xor_sync(0xffffffffu, l1, 2);
    float inv0 = 1.f / l0, inv1 = 1.f / l1;

    const int row0 = q0 + wid * 16 + (lane >> 2);
    const int colb = (lane & 3) * 2;
#pragma unroll
    for (int nt = 0; nt < 16; nt++) {
        int col = nt * 8 + colb;
        size_t i0 = (size_t)(b * Sn + row0) * Cn + h * Dn + col;
        size_t i1 = (size_t)(b * Sn + row0 + 8) * Cn + h * Dn + col;
        *(uint32_t*)&g_o[i0] = pack2h(o[nt][0] * inv0, o[nt][1] * inv0);
        *(uint32_t*)&g_o[i1] = pack2h(o[nt][2] * inv1, o[nt][3] * inv1);
    }
}

// ---------------- launch ----------------------------------------------------
extern "C" void kernel_launch(void* const* d_in, const int* in_sizes, int n_in,
                              void* d_out, int out_size)
{
    const float* x      = (const float*)d_in[0];
    const float* W_qkv  = (const float*)d_in[1];
    const float* q_w    = (const float*)d_in[2];
    const float* k_w    = (const float*)d_in[3];
    const float* W_proj = (const float*)d_in[4];
    const float* b_proj = (const float*)d_in[5];
    const float* fcos   = (const float*)d_in[6];
    const float* fsin   = (const float*)d_in[7];
    float* out = (float*)d_out;

    __half *p_x, *p_o, *p_wqh, *p_wql, *p_wph, *p_wpl;
    cudaGetSymbolAddress((void**)&p_x,   g_x);
    cudaGetSymbolAddress((void**)&p_o,   g_o);
    cudaGetSymbolAddress((void**)&p_wqh, g_wqkvT_h);
    cudaGetSymbolAddress((void**)&p_wql, g_wqkvT_l);
    cudaGetSymbolAddress((void**)&p_wph, g_wprojT_h);
    cudaGetSymbolAddress((void**)&p_wpl, g_wprojT_l);

    constexpr int GEMM_SMEM = 2 * STAGE_BYTES;            // 110592 B
    constexpr int ATTN_SMEM = AQT + 2 * 3 * ATILE;        // 139264 B
    static bool attr_set = false;
    if (!attr_set) {
        cudaFuncSetAttribute(gemm_mma, cudaFuncAttributeMaxDynamicSharedMemorySize, GEMM_SMEM);
        cudaFuncSetAttribute(gemm_qkv_fused, cudaFuncAttributeMaxDynamicSharedMemorySize, GEMM_SMEM);
        cudaFuncSetAttribute(attn_mma, cudaFuncAttributeMaxDynamicSharedMemorySize, ATTN_SMEM);
        attr_set = true;
    }

    // 0) operand conversions
    {
        int n = BSn * Cn;
        cvt_kernel<<<(n + 255) / 256, 256>>>(x, p_x, n);
        dim3 blk(32, 8);
        transpose_split_kernel<<<dim3(NQKV / 32, Cn / 32), blk>>>(W_qkv, p_wqh, p_wql, Cn, NQKV);
        transpose_split_kernel<<<dim3(Cn / 32, Cn / 32), blk>>>(W_proj, p_wph, p_wpl, Cn, Cn);
    }
    // 1) qkv = x @ W_qkv, fused with rmsnorm + rope
    {
        dim3 grid(NQKV / 128, BSn / 128);
        gemm_qkv_fused<<<grid, 256, GEMM_SMEM>>>(p_x, p_wqh, p_wql,
                                                 q_w, k_w, fcos, fsin, Cn);
    }
    // 2) attention (mma.sync fp16)
    {
        dim3 grid(Sn / 128, Bn * Hn);
        attn_mma<<<grid, 256, ATTN_SMEM>>>();
    }
    // 3) out = o @ W_proj + b_proj
    {
        dim3 grid(Cn / 128, BSn / 128);
        gemm_mma<<<grid, 256, GEMM_SMEM>>>(p_o, p_wph, p_wpl, b_proj, out,
                                           BSn, Cn, Cn);
    }
}